// round 2
// baseline (speedup 1.0000x reference)
#include <cuda_runtime.h>
#include <math_constants.h>
#include <cstddef>

// Problem constants
#define BB   4
#define CCH  256
#define NH   4
#define DH   64
#define GRP  8
#define HW   4096   // 64*64

// Scratch (device globals — no allocation allowed)
__device__ float g_qkv [(size_t)BB * 3 * CCH * HW];   // 48 MB  [b][768][4096]
__device__ float g_obuf[(size_t)BB * CCH * HW];       // 16 MB  [b][256][4096]
__device__ float g_mean[BB * GRP];
__device__ float g_rstd[BB * GRP];
__device__ float g_acoef[BB * CCH];
__device__ float g_bcoef[BB * CCH];

// ---------------------------------------------------------------------------
// Kernel 1: per-(batch, group) mean / rstd.  Group data is contiguous:
// x + (b*256 + g*32)*4096 = x + bid*131072, length 131072 floats.
// ---------------------------------------------------------------------------
__global__ void k_stats(const float* __restrict__ x) {
    const int bid = blockIdx.x;                        // 0..31 = b*8+g
    const float4* p = reinterpret_cast<const float4*>(x + (size_t)bid * 131072);
    float s = 0.f, s2 = 0.f;
    for (int i = threadIdx.x; i < 32768; i += 256) {
        float4 v = p[i];
        s  += v.x + v.y + v.z + v.w;
        s2 += v.x*v.x + v.y*v.y + v.z*v.z + v.w*v.w;
    }
    __shared__ float rs[256], rs2[256];
    rs[threadIdx.x] = s; rs2[threadIdx.x] = s2;
    __syncthreads();
    for (int off = 128; off > 0; off >>= 1) {
        if (threadIdx.x < off) {
            rs[threadIdx.x]  += rs[threadIdx.x + off];
            rs2[threadIdx.x] += rs2[threadIdx.x + off];
        }
        __syncthreads();
    }
    if (threadIdx.x == 0) {
        float mean = rs[0] * (1.f / 131072.f);
        float var  = rs2[0] * (1.f / 131072.f) - mean * mean;
        g_mean[bid] = mean;
        g_rstd[bid] = rsqrtf(var + 1e-5f);
    }
}

// ---------------------------------------------------------------------------
// Kernel 2: fold GroupNorm into per-(b,c) affine: h = x*a + bc
// ---------------------------------------------------------------------------
__global__ void k_coef(const float* __restrict__ nw, const float* __restrict__ nb) {
    int t = blockIdx.x * 256 + threadIdx.x;            // 0..1023
    if (t >= BB * CCH) return;
    int b = t >> 8, c = t & 255;
    int gidx = b * GRP + (c >> 5);
    float a = nw[c] * g_rstd[gidx];
    g_acoef[t] = a;
    g_bcoef[t] = nb[c] - g_mean[gidx] * a;
}

// ---------------------------------------------------------------------------
// Kernel 3/5: tiled fp32 GEMM over channels.
//   out[b][m][n] = sum_k W[m][k] * B[b][k][n] (+bias) (+resid)
// MODE 0: QKV — B operand = x with GroupNorm affine folded in, writes g_qkv.
// MODE 1: proj — B operand = g_obuf, writes `out` param with x residual.
// Tile: 64(M) x 64(N) x 16(K); 256 threads, 4x4 per thread.
// ---------------------------------------------------------------------------
template<int MODE>
__global__ void __launch_bounds__(256)
k_gemm(const float* __restrict__ W,
       const float* __restrict__ Bsrc,     // x (MODE 0) / unused (MODE 1)
       const float* __restrict__ bias,
       const float* __restrict__ resid,    // x (MODE 1)
       float* __restrict__ outp)           // unused (MODE 0) / d_out (MODE 1)
{
    __shared__ float As[64][17];
    __shared__ float Bs[16][68];
    const int t  = threadIdx.x;
    const int n0 = blockIdx.x * 64;
    const int m0 = blockIdx.y * 64;
    const int b  = blockIdx.z;
    const int r  = t >> 4;        // 0..15 -> rows m0 + 4r..
    const int q  = t & 15;        // 0..15 -> cols n0 + 4q..
    const int Mtot = (MODE == 0) ? 768 : 256;

    float acc[4][4] = {};

    const int alr = t >> 2;           // A tile row (0..63)
    const int alc = (t & 3) * 4;      // A tile col0
    const int blr = t >> 4;           // B tile row (0..15)
    const int blc = (t & 15) * 4;     // B tile col0

    for (int kk = 0; kk < 256; kk += 16) {
        // Load A tile (weights)
        float4 av = *reinterpret_cast<const float4*>(&W[(size_t)(m0 + alr) * 256 + kk + alc]);
        As[alr][alc + 0] = av.x; As[alr][alc + 1] = av.y;
        As[alr][alc + 2] = av.z; As[alr][alc + 3] = av.w;
        // Load B tile (activations)
        const int ch = kk + blr;
        float4 bv;
        if (MODE == 0) {
            bv = *reinterpret_cast<const float4*>(
                &Bsrc[((size_t)b * CCH + ch) * HW + n0 + blc]);
            float a  = g_acoef[b * CCH + ch];
            float bc = g_bcoef[b * CCH + ch];
            bv.x = bv.x * a + bc; bv.y = bv.y * a + bc;
            bv.z = bv.z * a + bc; bv.w = bv.w * a + bc;
        } else {
            bv = *reinterpret_cast<const float4*>(
                &g_obuf[((size_t)b * CCH + ch) * HW + n0 + blc]);
        }
        Bs[blr][blc + 0] = bv.x; Bs[blr][blc + 1] = bv.y;
        Bs[blr][blc + 2] = bv.z; Bs[blr][blc + 3] = bv.w;
        __syncthreads();

        #pragma unroll
        for (int kc = 0; kc < 16; kc++) {
            float a0 = As[r*4+0][kc], a1 = As[r*4+1][kc];
            float a2 = As[r*4+2][kc], a3 = As[r*4+3][kc];
            float b0 = Bs[kc][q*4+0], b1 = Bs[kc][q*4+1];
            float b2 = Bs[kc][q*4+2], b3 = Bs[kc][q*4+3];
            acc[0][0] += a0*b0; acc[0][1] += a0*b1; acc[0][2] += a0*b2; acc[0][3] += a0*b3;
            acc[1][0] += a1*b0; acc[1][1] += a1*b1; acc[1][2] += a1*b2; acc[1][3] += a1*b3;
            acc[2][0] += a2*b0; acc[2][1] += a2*b1; acc[2][2] += a2*b2; acc[2][3] += a2*b3;
            acc[3][0] += a3*b0; acc[3][1] += a3*b1; acc[3][2] += a3*b2; acc[3][3] += a3*b3;
        }
        __syncthreads();
    }

    // Epilogue
    #pragma unroll
    for (int mi = 0; mi < 4; mi++) {
        const int m = m0 + r * 4 + mi;
        const float bsv = bias[m];
        float4 v;
        v.x = acc[mi][0] + bsv; v.y = acc[mi][1] + bsv;
        v.z = acc[mi][2] + bsv; v.w = acc[mi][3] + bsv;
        const size_t off = ((size_t)b * Mtot + m) * HW + n0 + q * 4;
        if (MODE == 0) {
            *reinterpret_cast<float4*>(&g_qkv[off]) = v;
        } else {
            float4 xr = *reinterpret_cast<const float4*>(&resid[off]);
            v.x += xr.x; v.y += xr.y; v.z += xr.z; v.w += xr.w;
            *reinterpret_cast<float4*>(&outp[off]) = v;
        }
    }
}

// ---------------------------------------------------------------------------
// Kernel 4: flash attention, fp32.
// Layout: q/k/v are [d=64][seq=4096] per (b,h) inside g_qkv.
// Br=64 queries per block, Bc=32 keys per tile, 128 KV tiles.
// 256 threads: S-phase mapping 16x16 (4 rows x 2 cols per thread),
//              O-phase mapping 16x16 (4 rows x 4 chans per thread).
// ---------------------------------------------------------------------------
__global__ void __launch_bounds__(256) k_attn() {
    __shared__ float Qs[64][65];
    __shared__ float Ks[64][33];
    __shared__ float Vs[64][33];
    __shared__ float Ss[64][33];
    __shared__ float alpha_s[64];
    __shared__ float l_s[64];

    const int t  = threadIdx.x;
    const int bh = blockIdx.y;
    const int b  = bh >> 2, h = bh & 3;
    const int i0 = blockIdx.x * 64;

    const float* Qg = g_qkv + ((size_t)b * 768 +        h * DH) * HW + i0;
    const float* Kg = g_qkv + ((size_t)b * 768 + 256 +  h * DH) * HW;
    const float* Vg = g_qkv + ((size_t)b * 768 + 512 +  h * DH) * HW;

    // Load Q tile [64 d][64 i] (coalesced in i)
    #pragma unroll
    for (int l = 0; l < 16; l++) {
        int idx = l * 256 + t;
        int c = idx >> 6, i = idx & 63;
        Qs[c][i] = Qg[(size_t)c * HW + i];
    }

    const int r = t >> 4;     // 0..15
    const int q = t & 15;     // 0..15
    float m_r = -CUDART_INF_F, l_r = 0.f;
    float acc[4][4] = {};
    const float scale = 0.125f;   // d^-0.5 = 1/8

    for (int jt = 0; jt < 128; jt++) {
        const int j0 = jt * 32;
        #pragma unroll
        for (int l = 0; l < 8; l++) {
            int idx = l * 256 + t;
            int c = idx >> 5, j = idx & 31;
            Ks[c][j] = Kg[(size_t)c * HW + j0 + j];
            Vs[c][j] = Vg[(size_t)c * HW + j0 + j];
        }
        __syncthreads();

        // S[i][j] = scale * sum_c Q[c][i] K[c][j]
        float s00=0.f,s01=0.f,s10=0.f,s11=0.f,s20=0.f,s21=0.f,s30=0.f,s31=0.f;
        #pragma unroll
        for (int c = 0; c < 64; c++) {
            float q0 = Qs[c][r*4+0], q1 = Qs[c][r*4+1];
            float q2 = Qs[c][r*4+2], q3 = Qs[c][r*4+3];
            float k0 = Ks[c][q*2+0], k1 = Ks[c][q*2+1];
            s00 += q0*k0; s01 += q0*k1;
            s10 += q1*k0; s11 += q1*k1;
            s20 += q2*k0; s21 += q2*k1;
            s30 += q3*k0; s31 += q3*k1;
        }
        Ss[r*4+0][q*2+0] = s00*scale; Ss[r*4+0][q*2+1] = s01*scale;
        Ss[r*4+1][q*2+0] = s10*scale; Ss[r*4+1][q*2+1] = s11*scale;
        Ss[r*4+2][q*2+0] = s20*scale; Ss[r*4+2][q*2+1] = s21*scale;
        Ss[r*4+3][q*2+0] = s30*scale; Ss[r*4+3][q*2+1] = s31*scale;
        __syncthreads();

        // Online softmax, one thread per row (threads 0..63)
        if (t < 64) {
            float mloc = -CUDART_INF_F;
            #pragma unroll
            for (int j = 0; j < 32; j++) mloc = fmaxf(mloc, Ss[t][j]);
            float mnew = fmaxf(m_r, mloc);
            float al   = __expf(m_r - mnew);     // -inf on first tile -> 0
            float sum  = 0.f;
            #pragma unroll
            for (int j = 0; j < 32; j++) {
                float p = __expf(Ss[t][j] - mnew);
                Ss[t][j] = p;
                sum += p;
            }
            l_r = l_r * al + sum;
            m_r = mnew;
            alpha_s[t] = al;
        }
        __syncthreads();

        // O[i][c] = O*alpha + P @ V^T   (thread: rows 4r.., chans 4q..)
        float al0 = alpha_s[r*4+0], al1 = alpha_s[r*4+1];
        float al2 = alpha_s[r*4+2], al3 = alpha_s[r*4+3];
        #pragma unroll
        for (int cc = 0; cc < 4; cc++) {
            acc[0][cc] *= al0; acc[1][cc] *= al1;
            acc[2][cc] *= al2; acc[3][cc] *= al3;
        }
        #pragma unroll
        for (int j = 0; j < 32; j++) {
            float p0 = Ss[r*4+0][j], p1 = Ss[r*4+1][j];
            float p2 = Ss[r*4+2][j], p3 = Ss[r*4+3][j];
            float v0 = Vs[q*4+0][j], v1 = Vs[q*4+1][j];
            float v2 = Vs[q*4+2][j], v3 = Vs[q*4+3][j];
            acc[0][0] += p0*v0; acc[0][1] += p0*v1; acc[0][2] += p0*v2; acc[0][3] += p0*v3;
            acc[1][0] += p1*v0; acc[1][1] += p1*v1; acc[1][2] += p1*v2; acc[1][3] += p1*v3;
            acc[2][0] += p2*v0; acc[2][1] += p2*v1; acc[2][2] += p2*v2; acc[2][3] += p2*v3;
            acc[3][0] += p3*v0; acc[3][1] += p3*v1; acc[3][2] += p3*v2; acc[3][3] += p3*v3;
        }
        __syncthreads();
    }

    if (t < 64) l_s[t] = l_r;
    __syncthreads();
    float r0 = 1.f / l_s[r*4+0], r1 = 1.f / l_s[r*4+1];
    float r2 = 1.f / l_s[r*4+2], r3 = 1.f / l_s[r*4+3];

    float* Og = g_obuf + ((size_t)b * CCH + h * DH) * HW + i0;
    #pragma unroll
    for (int cc = 0; cc < 4; cc++) {
        float* col = Og + (size_t)(q*4+cc) * HW + r*4;
        col[0] = acc[0][cc] * r0;
        col[1] = acc[1][cc] * r1;
        col[2] = acc[2][cc] * r2;
        col[3] = acc[3][cc] * r3;
    }
}

// ---------------------------------------------------------------------------
extern "C" void kernel_launch(void* const* d_in, const int* in_sizes, int n_in,
                              void* d_out, int out_size) {
    const float* x      = (const float*)d_in[0];
    const float* norm_w = (const float*)d_in[1];
    const float* norm_b = (const float*)d_in[2];
    const float* qkv_w  = (const float*)d_in[3];
    const float* qkv_b  = (const float*)d_in[4];
    const float* proj_w = (const float*)d_in[5];
    const float* proj_b = (const float*)d_in[6];
    float* out = (float*)d_out;

    k_stats<<<32, 256>>>(x);
    k_coef<<<4, 256>>>(norm_w, norm_b);
    k_gemm<0><<<dim3(HW/64, 768/64, BB), 256>>>(qkv_w, x, qkv_b, nullptr, nullptr);
    k_attn<<<dim3(HW/64, BB*NH), 256>>>();
    k_gemm<1><<<dim3(HW/64, CCH/64, BB), 256>>>(proj_w, nullptr, proj_b, x, out);
}

// round 3
// speedup vs baseline: 2.6377x; 2.6377x over previous
#include <cuda_runtime.h>
#include <math_constants.h>
#include <cstddef>

// Problem constants
#define BB   4
#define CCH  256
#define NH   4
#define DH   64
#define GRP  8
#define HW   4096   // 64*64

// Scratch (device globals — no allocation allowed)
__device__ float g_qkv [(size_t)BB * 3 * CCH * HW];   // 48 MB  [b][768][4096]
__device__ float g_obuf[(size_t)BB * CCH * HW];       // 16 MB  [b][256][4096]
__device__ float g_mean[BB * GRP];
__device__ float g_rstd[BB * GRP];
__device__ float g_acoef[BB * CCH];
__device__ float g_bcoef[BB * CCH];

// ---------------------------------------------------------------------------
// Kernel 1: per-(batch, group) mean / rstd
// ---------------------------------------------------------------------------
__global__ void k_stats(const float* __restrict__ x) {
    const int bid = blockIdx.x;                        // 0..31 = b*8+g
    const float4* p = reinterpret_cast<const float4*>(x + (size_t)bid * 131072);
    float s = 0.f, s2 = 0.f;
    for (int i = threadIdx.x; i < 32768; i += 256) {
        float4 v = p[i];
        s  += v.x + v.y + v.z + v.w;
        s2 += v.x*v.x + v.y*v.y + v.z*v.z + v.w*v.w;
    }
    __shared__ float rs[256], rs2[256];
    rs[threadIdx.x] = s; rs2[threadIdx.x] = s2;
    __syncthreads();
    for (int off = 128; off > 0; off >>= 1) {
        if (threadIdx.x < off) {
            rs[threadIdx.x]  += rs[threadIdx.x + off];
            rs2[threadIdx.x] += rs2[threadIdx.x + off];
        }
        __syncthreads();
    }
    if (threadIdx.x == 0) {
        float mean = rs[0] * (1.f / 131072.f);
        float var  = rs2[0] * (1.f / 131072.f) - mean * mean;
        g_mean[bid] = mean;
        g_rstd[bid] = rsqrtf(var + 1e-5f);
    }
}

// ---------------------------------------------------------------------------
// Kernel 2: fold GroupNorm into per-(b,c) affine: h = x*a + bc
// ---------------------------------------------------------------------------
__global__ void k_coef(const float* __restrict__ nw, const float* __restrict__ nb) {
    int t = blockIdx.x * 256 + threadIdx.x;
    if (t >= BB * CCH) return;
    int b = t >> 8, c = t & 255;
    int gidx = b * GRP + (c >> 5);
    float a = nw[c] * g_rstd[gidx];
    g_acoef[t] = a;
    g_bcoef[t] = nb[c] - g_mean[gidx] * a;
}

// ---------------------------------------------------------------------------
// Kernel 3/5: tiled fp32 GEMM (unchanged from passing baseline)
// ---------------------------------------------------------------------------
template<int MODE>
__global__ void __launch_bounds__(256)
k_gemm(const float* __restrict__ W,
       const float* __restrict__ Bsrc,
       const float* __restrict__ bias,
       const float* __restrict__ resid,
       float* __restrict__ outp)
{
    __shared__ float As[64][17];
    __shared__ float Bs[16][68];
    const int t  = threadIdx.x;
    const int n0 = blockIdx.x * 64;
    const int m0 = blockIdx.y * 64;
    const int b  = blockIdx.z;
    const int r  = t >> 4;
    const int q  = t & 15;
    const int Mtot = (MODE == 0) ? 768 : 256;

    float acc[4][4] = {};

    const int alr = t >> 2;
    const int alc = (t & 3) * 4;
    const int blr = t >> 4;
    const int blc = (t & 15) * 4;

    for (int kk = 0; kk < 256; kk += 16) {
        float4 av = *reinterpret_cast<const float4*>(&W[(size_t)(m0 + alr) * 256 + kk + alc]);
        As[alr][alc + 0] = av.x; As[alr][alc + 1] = av.y;
        As[alr][alc + 2] = av.z; As[alr][alc + 3] = av.w;
        const int ch = kk + blr;
        float4 bv;
        if (MODE == 0) {
            bv = *reinterpret_cast<const float4*>(
                &Bsrc[((size_t)b * CCH + ch) * HW + n0 + blc]);
            float a  = g_acoef[b * CCH + ch];
            float bc = g_bcoef[b * CCH + ch];
            bv.x = bv.x * a + bc; bv.y = bv.y * a + bc;
            bv.z = bv.z * a + bc; bv.w = bv.w * a + bc;
        } else {
            bv = *reinterpret_cast<const float4*>(
                &g_obuf[((size_t)b * CCH + ch) * HW + n0 + blc]);
        }
        Bs[blr][blc + 0] = bv.x; Bs[blr][blc + 1] = bv.y;
        Bs[blr][blc + 2] = bv.z; Bs[blr][blc + 3] = bv.w;
        __syncthreads();

        #pragma unroll
        for (int kc = 0; kc < 16; kc++) {
            float a0 = As[r*4+0][kc], a1 = As[r*4+1][kc];
            float a2 = As[r*4+2][kc], a3 = As[r*4+3][kc];
            float b0 = Bs[kc][q*4+0], b1 = Bs[kc][q*4+1];
            float b2 = Bs[kc][q*4+2], b3 = Bs[kc][q*4+3];
            acc[0][0] += a0*b0; acc[0][1] += a0*b1; acc[0][2] += a0*b2; acc[0][3] += a0*b3;
            acc[1][0] += a1*b0; acc[1][1] += a1*b1; acc[1][2] += a1*b2; acc[1][3] += a1*b3;
            acc[2][0] += a2*b0; acc[2][1] += a2*b1; acc[2][2] += a2*b2; acc[2][3] += a2*b3;
            acc[3][0] += a3*b0; acc[3][1] += a3*b1; acc[3][2] += a3*b2; acc[3][3] += a3*b3;
        }
        __syncthreads();
    }

    #pragma unroll
    for (int mi = 0; mi < 4; mi++) {
        const int m = m0 + r * 4 + mi;
        const float bsv = bias[m];
        float4 v;
        v.x = acc[mi][0] + bsv; v.y = acc[mi][1] + bsv;
        v.z = acc[mi][2] + bsv; v.w = acc[mi][3] + bsv;
        const size_t off = ((size_t)b * Mtot + m) * HW + n0 + q * 4;
        if (MODE == 0) {
            *reinterpret_cast<float4*>(&g_qkv[off]) = v;
        } else {
            float4 xr = *reinterpret_cast<const float4*>(&resid[off]);
            v.x += xr.x; v.y += xr.y; v.z += xr.z; v.w += xr.w;
            *reinterpret_cast<float4*>(&outp[off]) = v;
        }
    }
}

// ---------------------------------------------------------------------------
// Kernel 4: flash attention on tensor cores (mma.sync tf32, fp32 accum).
// Br=128 queries/block, Bc=64 keys/tile, 8 warps (each owns 16 query rows).
// Q fragments live in registers for the whole kernel.
// Layouts (global): q/k/v are [d=64][seq=4096] per (b,h).
// smem: Ks[64][72], Vs[64][68] (tf32-rounded), Ps[8 warps][16][68].
// ---------------------------------------------------------------------------
#define KS_STRIDE 72
#define VS_STRIDE 68
#define PS_STRIDE 68
#define SMEM_ATTN_FLOATS (64*KS_STRIDE + 64*VS_STRIDE + 128*PS_STRIDE)

__device__ __forceinline__ unsigned f2tf(float f) {
    unsigned u;
    asm("cvt.rna.tf32.f32 %0, %1;" : "=r"(u) : "f"(f));
    return u;
}

__device__ __forceinline__ void mma_tf32(float c[4], const unsigned a[4],
                                         unsigned b0, unsigned b1) {
    asm volatile(
        "mma.sync.aligned.m16n8k8.row.col.f32.tf32.tf32.f32 "
        "{%0,%1,%2,%3}, {%4,%5,%6,%7}, {%8,%9}, {%0,%1,%2,%3};"
        : "+f"(c[0]), "+f"(c[1]), "+f"(c[2]), "+f"(c[3])
        : "r"(a[0]), "r"(a[1]), "r"(a[2]), "r"(a[3]), "r"(b0), "r"(b1));
}

__global__ void __launch_bounds__(256, 1) k_attn() {
    extern __shared__ float smem[];
    float* Ks = smem;                       // [64][72]
    float* Vs = Ks + 64 * KS_STRIDE;        // [64][68]
    float* Ps = Vs + 64 * VS_STRIDE;        // [128][68] (per-warp 16-row slices)

    const int t    = threadIdx.x;
    const int w    = t >> 5;
    const int lane = t & 31;
    const int gr   = lane >> 2;   // 0..7
    const int gc   = lane & 3;    // 0..3

    const int bh = blockIdx.y;
    const int b  = bh >> 2, h = bh & 3;
    const int i0 = blockIdx.x * 128;
    const int iw = i0 + w * 16;   // this warp's first query row

    const float* Qg = g_qkv + ((size_t)b * 768 +       h * DH) * HW;
    const float* Kg = g_qkv + ((size_t)b * 768 + 256 + h * DH) * HW;
    const float* Vg = g_qkv + ((size_t)b * 768 + 512 + h * DH) * HW;

    // ---- Q A-fragments in registers (scaled by d^-0.5, tf32-rounded) ----
    const float scale = 0.125f;
    unsigned Aq[8][4];
    #pragma unroll
    for (int kk = 0; kk < 8; kk++) {
        const int c0 = kk * 8 + gc;
        const int c1 = c0 + 4;
        Aq[kk][0] = f2tf(Qg[(size_t)c0 * HW + iw + gr    ] * scale);
        Aq[kk][1] = f2tf(Qg[(size_t)c0 * HW + iw + gr + 8] * scale);
        Aq[kk][2] = f2tf(Qg[(size_t)c1 * HW + iw + gr    ] * scale);
        Aq[kk][3] = f2tf(Qg[(size_t)c1 * HW + iw + gr + 8] * scale);
    }

    float Oacc[8][4];
    #pragma unroll
    for (int i = 0; i < 8; i++)
        #pragma unroll
        for (int j = 0; j < 4; j++) Oacc[i][j] = 0.f;

    float m0 = -CUDART_INF_F, m1 = -CUDART_INF_F;
    float l0 = 0.f, l1 = 0.f;

    float* Pw = Ps + w * 16 * PS_STRIDE;

    for (int jt = 0; jt < 64; jt++) {
        const int j0 = jt * 64;
        __syncthreads();   // previous iteration's Ks/Vs reads complete

        // ---- fill K/V tiles (tf32-rounded), coalesced float4 loads ----
        #pragma unroll
        for (int l = 0; l < 4; l++) {
            const int idx4 = l * 256 + t;             // 0..1023
            const int c  = idx4 >> 4;                 // 0..63
            const int jv = (idx4 & 15) * 4;           // 0..60
            float4 kv = *reinterpret_cast<const float4*>(&Kg[(size_t)c * HW + j0 + jv]);
            float4 vv = *reinterpret_cast<const float4*>(&Vg[(size_t)c * HW + j0 + jv]);
            float4 ko, vo;
            ko.x = __uint_as_float(f2tf(kv.x)); ko.y = __uint_as_float(f2tf(kv.y));
            ko.z = __uint_as_float(f2tf(kv.z)); ko.w = __uint_as_float(f2tf(kv.w));
            vo.x = __uint_as_float(f2tf(vv.x)); vo.y = __uint_as_float(f2tf(vv.y));
            vo.z = __uint_as_float(f2tf(vv.z)); vo.w = __uint_as_float(f2tf(vv.w));
            *reinterpret_cast<float4*>(&Ks[c * KS_STRIDE + jv]) = ko;
            *reinterpret_cast<float4*>(&Vs[c * VS_STRIDE + jv]) = vo;
        }
        __syncthreads();

        // ---- S = (Q^T K) [16 x 64] per warp, tensor cores ----
        float S[8][4];
        #pragma unroll
        for (int nt = 0; nt < 8; nt++) {
            S[nt][0] = 0.f; S[nt][1] = 0.f; S[nt][2] = 0.f; S[nt][3] = 0.f;
        }
        #pragma unroll
        for (int nt = 0; nt < 8; nt++) {
            const int jb = nt * 8 + gr;
            #pragma unroll
            for (int kk = 0; kk < 8; kk++) {
                unsigned b0 = __float_as_uint(Ks[(kk * 8 + gc    ) * KS_STRIDE + jb]);
                unsigned b1 = __float_as_uint(Ks[(kk * 8 + gc + 4) * KS_STRIDE + jb]);
                mma_tf32(S[nt], Aq[kk], b0, b1);
            }
        }

        // ---- online softmax in registers (rows gr and gr+8) ----
        float mx0 = -CUDART_INF_F, mx1 = -CUDART_INF_F;
        #pragma unroll
        for (int nt = 0; nt < 8; nt++) {
            mx0 = fmaxf(mx0, fmaxf(S[nt][0], S[nt][1]));
            mx1 = fmaxf(mx1, fmaxf(S[nt][2], S[nt][3]));
        }
        mx0 = fmaxf(mx0, __shfl_xor_sync(0xffffffffu, mx0, 1));
        mx0 = fmaxf(mx0, __shfl_xor_sync(0xffffffffu, mx0, 2));
        mx1 = fmaxf(mx1, __shfl_xor_sync(0xffffffffu, mx1, 1));
        mx1 = fmaxf(mx1, __shfl_xor_sync(0xffffffffu, mx1, 2));

        const float mn0 = fmaxf(m0, mx0);
        const float mn1 = fmaxf(m1, mx1);
        const float al0 = __expf(m0 - mn0);
        const float al1 = __expf(m1 - mn1);
        float s0 = 0.f, s1 = 0.f;
        #pragma unroll
        for (int nt = 0; nt < 8; nt++) {
            float p0 = __expf(S[nt][0] - mn0);
            float p1 = __expf(S[nt][1] - mn0);
            float p2 = __expf(S[nt][2] - mn1);
            float p3 = __expf(S[nt][3] - mn1);
            S[nt][0] = p0; S[nt][1] = p1; S[nt][2] = p2; S[nt][3] = p3;
            s0 += p0 + p1; s1 += p2 + p3;
        }
        s0 += __shfl_xor_sync(0xffffffffu, s0, 1);
        s0 += __shfl_xor_sync(0xffffffffu, s0, 2);
        s1 += __shfl_xor_sync(0xffffffffu, s1, 1);
        s1 += __shfl_xor_sync(0xffffffffu, s1, 2);
        l0 = l0 * al0 + s0;  m0 = mn0;
        l1 = l1 * al1 + s1;  m1 = mn1;

        #pragma unroll
        for (int ct = 0; ct < 8; ct++) {
            Oacc[ct][0] *= al0; Oacc[ct][1] *= al0;
            Oacc[ct][2] *= al1; Oacc[ct][3] *= al1;
        }

        // ---- P (tf32) -> per-warp smem, then A-fragments for P@V^T ----
        #pragma unroll
        for (int nt = 0; nt < 8; nt++) {
            const int col = nt * 8 + gc * 2;
            Pw[ gr      * PS_STRIDE + col    ] = __uint_as_float(f2tf(S[nt][0]));
            Pw[ gr      * PS_STRIDE + col + 1] = __uint_as_float(f2tf(S[nt][1]));
            Pw[(gr + 8) * PS_STRIDE + col    ] = __uint_as_float(f2tf(S[nt][2]));
            Pw[(gr + 8) * PS_STRIDE + col + 1] = __uint_as_float(f2tf(S[nt][3]));
        }
        __syncwarp();

        #pragma unroll
        for (int kk = 0; kk < 8; kk++) {
            unsigned pa[4];
            pa[0] = __float_as_uint(Pw[ gr      * PS_STRIDE + kk * 8 + gc    ]);
            pa[1] = __float_as_uint(Pw[(gr + 8) * PS_STRIDE + kk * 8 + gc    ]);
            pa[2] = __float_as_uint(Pw[ gr      * PS_STRIDE + kk * 8 + gc + 4]);
            pa[3] = __float_as_uint(Pw[(gr + 8) * PS_STRIDE + kk * 8 + gc + 4]);
            #pragma unroll
            for (int ct = 0; ct < 8; ct++) {
                unsigned b0 = __float_as_uint(Vs[(ct * 8 + gr) * VS_STRIDE + kk * 8 + gc    ]);
                unsigned b1 = __float_as_uint(Vs[(ct * 8 + gr) * VS_STRIDE + kk * 8 + gc + 4]);
                mma_tf32(Oacc[ct], pa, b0, b1);
            }
        }
    }

    // ---- epilogue: normalize and write O [d][seq] ----
    const float inv0 = 1.f / l0;
    const float inv1 = 1.f / l1;
    float* Og = g_obuf + ((size_t)b * CCH + h * DH) * HW;
    #pragma unroll
    for (int ct = 0; ct < 8; ct++) {
        const int c = ct * 8 + gc * 2;
        Og[(size_t)(c    ) * HW + iw + gr    ] = Oacc[ct][0] * inv0;
        Og[(size_t)(c + 1) * HW + iw + gr    ] = Oacc[ct][1] * inv0;
        Og[(size_t)(c    ) * HW + iw + gr + 8] = Oacc[ct][2] * inv1;
        Og[(size_t)(c + 1) * HW + iw + gr + 8] = Oacc[ct][3] * inv1;
    }
}

// ---------------------------------------------------------------------------
extern "C" void kernel_launch(void* const* d_in, const int* in_sizes, int n_in,
                              void* d_out, int out_size) {
    const float* x      = (const float*)d_in[0];
    const float* norm_w = (const float*)d_in[1];
    const float* norm_b = (const float*)d_in[2];
    const float* qkv_w  = (const float*)d_in[3];
    const float* qkv_b  = (const float*)d_in[4];
    const float* proj_w = (const float*)d_in[5];
    const float* proj_b = (const float*)d_in[6];
    float* out = (float*)d_out;

    const int smem_bytes = SMEM_ATTN_FLOATS * 4;   // 70656
    cudaFuncSetAttribute(k_attn, cudaFuncAttributeMaxDynamicSharedMemorySize, smem_bytes);

    k_stats<<<32, 256>>>(x);
    k_coef<<<4, 256>>>(norm_w, norm_b);
    k_gemm<0><<<dim3(HW/64, 768/64, BB), 256>>>(qkv_w, x, qkv_b, nullptr, nullptr);
    k_attn<<<dim3(HW/128, BB*NH), 256, smem_bytes>>>();
    k_gemm<1><<<dim3(HW/64, CCH/64, BB), 256>>>(proj_w, nullptr, proj_b, x, out);
}

// round 4
// speedup vs baseline: 4.0539x; 1.5369x over previous
#include <cuda_runtime.h>
#include <cuda_fp16.h>
#include <math_constants.h>
#include <cstddef>

// Problem constants
#define BB   4
#define CCH  256
#define NH   4
#define DH   64
#define GRP  8
#define HW   4096   // 64*64

// Scratch (device globals — no allocation allowed)
__device__ float g_qkv [(size_t)BB * 3 * CCH * HW];   // 48 MB  [b][768][4096]
__device__ float g_obuf[(size_t)BB * CCH * HW];       // 16 MB  [b][256][4096]
__device__ float g_mean[BB * GRP];
__device__ float g_rstd[BB * GRP];
__device__ float g_acoef[BB * CCH];
__device__ float g_bcoef[BB * CCH];

// ---------------------------------------------------------------------------
// Kernel 1: per-(batch, group) mean / rstd
// ---------------------------------------------------------------------------
__global__ void k_stats(const float* __restrict__ x) {
    const int bid = blockIdx.x;                        // 0..31 = b*8+g
    const float4* p = reinterpret_cast<const float4*>(x + (size_t)bid * 131072);
    float s = 0.f, s2 = 0.f;
    for (int i = threadIdx.x; i < 32768; i += 256) {
        float4 v = p[i];
        s  += v.x + v.y + v.z + v.w;
        s2 += v.x*v.x + v.y*v.y + v.z*v.z + v.w*v.w;
    }
    __shared__ float rs[256], rs2[256];
    rs[threadIdx.x] = s; rs2[threadIdx.x] = s2;
    __syncthreads();
    for (int off = 128; off > 0; off >>= 1) {
        if (threadIdx.x < off) {
            rs[threadIdx.x]  += rs[threadIdx.x + off];
            rs2[threadIdx.x] += rs2[threadIdx.x + off];
        }
        __syncthreads();
    }
    if (threadIdx.x == 0) {
        float mean = rs[0] * (1.f / 131072.f);
        float var  = rs2[0] * (1.f / 131072.f) - mean * mean;
        g_mean[bid] = mean;
        g_rstd[bid] = rsqrtf(var + 1e-5f);
    }
}

// ---------------------------------------------------------------------------
// Kernel 2: fold GroupNorm into per-(b,c) affine: h = x*a + bc
// ---------------------------------------------------------------------------
__global__ void k_coef(const float* __restrict__ nw, const float* __restrict__ nb) {
    int t = blockIdx.x * 256 + threadIdx.x;
    if (t >= BB * CCH) return;
    int b = t >> 8, c = t & 255;
    int gidx = b * GRP + (c >> 5);
    float a = nw[c] * g_rstd[gidx];
    g_acoef[t] = a;
    g_bcoef[t] = nb[c] - g_mean[gidx] * a;
}

// ---------------------------------------------------------------------------
// Kernel 3/5: tiled fp32 GEMM (unchanged, known-correct)
// ---------------------------------------------------------------------------
template<int MODE>
__global__ void __launch_bounds__(256)
k_gemm(const float* __restrict__ W,
       const float* __restrict__ Bsrc,
       const float* __restrict__ bias,
       const float* __restrict__ resid,
       float* __restrict__ outp)
{
    __shared__ float As[64][17];
    __shared__ float Bs[16][68];
    const int t  = threadIdx.x;
    const int n0 = blockIdx.x * 64;
    const int m0 = blockIdx.y * 64;
    const int b  = blockIdx.z;
    const int r  = t >> 4;
    const int q  = t & 15;
    const int Mtot = (MODE == 0) ? 768 : 256;

    float acc[4][4] = {};

    const int alr = t >> 2;
    const int alc = (t & 3) * 4;
    const int blr = t >> 4;
    const int blc = (t & 15) * 4;

    for (int kk = 0; kk < 256; kk += 16) {
        float4 av = *reinterpret_cast<const float4*>(&W[(size_t)(m0 + alr) * 256 + kk + alc]);
        As[alr][alc + 0] = av.x; As[alr][alc + 1] = av.y;
        As[alr][alc + 2] = av.z; As[alr][alc + 3] = av.w;
        const int ch = kk + blr;
        float4 bv;
        if (MODE == 0) {
            bv = *reinterpret_cast<const float4*>(
                &Bsrc[((size_t)b * CCH + ch) * HW + n0 + blc]);
            float a  = g_acoef[b * CCH + ch];
            float bc = g_bcoef[b * CCH + ch];
            bv.x = bv.x * a + bc; bv.y = bv.y * a + bc;
            bv.z = bv.z * a + bc; bv.w = bv.w * a + bc;
        } else {
            bv = *reinterpret_cast<const float4*>(
                &g_obuf[((size_t)b * CCH + ch) * HW + n0 + blc]);
        }
        Bs[blr][blc + 0] = bv.x; Bs[blr][blc + 1] = bv.y;
        Bs[blr][blc + 2] = bv.z; Bs[blr][blc + 3] = bv.w;
        __syncthreads();

        #pragma unroll
        for (int kc = 0; kc < 16; kc++) {
            float a0 = As[r*4+0][kc], a1 = As[r*4+1][kc];
            float a2 = As[r*4+2][kc], a3 = As[r*4+3][kc];
            float b0 = Bs[kc][q*4+0], b1 = Bs[kc][q*4+1];
            float b2 = Bs[kc][q*4+2], b3 = Bs[kc][q*4+3];
            acc[0][0] += a0*b0; acc[0][1] += a0*b1; acc[0][2] += a0*b2; acc[0][3] += a0*b3;
            acc[1][0] += a1*b0; acc[1][1] += a1*b1; acc[1][2] += a1*b2; acc[1][3] += a1*b3;
            acc[2][0] += a2*b0; acc[2][1] += a2*b1; acc[2][2] += a2*b2; acc[2][3] += a2*b3;
            acc[3][0] += a3*b0; acc[3][1] += a3*b1; acc[3][2] += a3*b2; acc[3][3] += a3*b3;
        }
        __syncthreads();
    }

    #pragma unroll
    for (int mi = 0; mi < 4; mi++) {
        const int m = m0 + r * 4 + mi;
        const float bsv = bias[m];
        float4 v;
        v.x = acc[mi][0] + bsv; v.y = acc[mi][1] + bsv;
        v.z = acc[mi][2] + bsv; v.w = acc[mi][3] + bsv;
        const size_t off = ((size_t)b * Mtot + m) * HW + n0 + q * 4;
        if (MODE == 0) {
            *reinterpret_cast<float4*>(&g_qkv[off]) = v;
        } else {
            float4 xr = *reinterpret_cast<const float4*>(&resid[off]);
            v.x += xr.x; v.y += xr.y; v.z += xr.z; v.w += xr.w;
            *reinterpret_cast<float4*>(&outp[off]) = v;
        }
    }
}

// ---------------------------------------------------------------------------
// Kernel 4: flash attention, fp16 mma.sync m16n8k16 (fp32 accum).
// Br=128 (8 warps x 16 rows), Bc=64, 64 KV tiles. Base-2 online softmax.
// Q fragments in registers; P fed to PV mma directly from S C-fragments
// (no smem round-trip). K/V in smem as half, natural [c][j], stride 72.
// ---------------------------------------------------------------------------
#define KV_STRIDE 72

__device__ __forceinline__ float ex2f(float x) {
    float y;
    asm("ex2.approx.f32 %0, %1;" : "=f"(y) : "f"(x));
    return y;
}

__device__ __forceinline__ unsigned h2u(__half2 h) {
    return *reinterpret_cast<unsigned*>(&h);
}

__device__ __forceinline__ void mma_f16(float c[4], const unsigned a[4],
                                        unsigned b0, unsigned b1) {
    asm volatile(
        "mma.sync.aligned.m16n8k16.row.col.f32.f16.f16.f32 "
        "{%0,%1,%2,%3}, {%4,%5,%6,%7}, {%8,%9}, {%0,%1,%2,%3};"
        : "+f"(c[0]), "+f"(c[1]), "+f"(c[2]), "+f"(c[3])
        : "r"(a[0]), "r"(a[1]), "r"(a[2]), "r"(a[3]), "r"(b0), "r"(b1));
}

__global__ void __launch_bounds__(256, 2) k_attn() {
    __shared__ __half Ks[64 * KV_STRIDE];
    __shared__ __half Vs[64 * KV_STRIDE];

    const int t    = threadIdx.x;
    const int w    = t >> 5;
    const int lane = t & 31;
    const int gr   = lane >> 2;   // 0..7
    const int gc   = lane & 3;    // 0..3

    const int bh = blockIdx.y;
    const int b  = bh >> 2, h = bh & 3;
    const int i0 = blockIdx.x * 128;
    const int iw = i0 + w * 16;   // this warp's first query row

    const float* Qg = g_qkv + ((size_t)b * 768 +       h * DH) * HW;
    const float* Kg = g_qkv + ((size_t)b * 768 + 256 + h * DH) * HW;
    const float* Vg = g_qkv + ((size_t)b * 768 + 512 + h * DH) * HW;

    // Q A-fragments (scale * log2(e) folded in; softmax done base-2)
    const float qscale = 0.125f * 1.44269504088896341f;
    unsigned Aq[4][4];
    #pragma unroll
    for (int kk = 0; kk < 4; kk++) {
        const int c0 = kk * 16 + 2 * gc;
        #pragma unroll
        for (int half8 = 0; half8 < 2; half8++) {   // cols +0 / +8
            const int c = c0 + half8 * 8;
            float qlo0 = Qg[(size_t)(c    ) * HW + iw + gr] * qscale;
            float qhi0 = Qg[(size_t)(c + 1) * HW + iw + gr] * qscale;
            float qlo1 = Qg[(size_t)(c    ) * HW + iw + gr + 8] * qscale;
            float qhi1 = Qg[(size_t)(c + 1) * HW + iw + gr + 8] * qscale;
            Aq[kk][half8 * 2 + 0] = h2u(__floats2half2_rn(qlo0, qhi0));
            Aq[kk][half8 * 2 + 1] = h2u(__floats2half2_rn(qlo1, qhi1));
        }
    }

    float Oacc[8][4];
    #pragma unroll
    for (int i = 0; i < 8; i++) {
        Oacc[i][0] = 0.f; Oacc[i][1] = 0.f; Oacc[i][2] = 0.f; Oacc[i][3] = 0.f;
    }
    float m0 = -CUDART_INF_F, m1 = -CUDART_INF_F;
    float l0 = 0.f, l1 = 0.f;

    for (int jt = 0; jt < 64; jt++) {
        const int j0 = jt * 64;
        __syncthreads();   // protect previous tile's reads

        // fill K/V tiles (half), coalesced float4 loads, uint2 stores
        #pragma unroll
        for (int l = 0; l < 4; l++) {
            const int idx = l * 256 + t;              // 0..1023
            const int c   = idx >> 4;                 // 0..63
            const int jv  = (idx & 15) * 4;           // 0..60
            float4 kv = *reinterpret_cast<const float4*>(&Kg[(size_t)c * HW + j0 + jv]);
            float4 vv = *reinterpret_cast<const float4*>(&Vg[(size_t)c * HW + j0 + jv]);
            __half2 k01 = __floats2half2_rn(kv.x, kv.y);
            __half2 k23 = __floats2half2_rn(kv.z, kv.w);
            __half2 v01 = __floats2half2_rn(vv.x, vv.y);
            __half2 v23 = __floats2half2_rn(vv.z, vv.w);
            uint2 kw = make_uint2(h2u(k01), h2u(k23));
            uint2 vw = make_uint2(h2u(v01), h2u(v23));
            *reinterpret_cast<uint2*>(&Ks[c * KV_STRIDE + jv]) = kw;
            *reinterpret_cast<uint2*>(&Vs[c * KV_STRIDE + jv]) = vw;
        }
        __syncthreads();

        // ---- S = Q K^T [16 x 64] per warp ----
        float S[8][4];
        #pragma unroll
        for (int nt = 0; nt < 8; nt++) {
            S[nt][0] = 0.f; S[nt][1] = 0.f; S[nt][2] = 0.f; S[nt][3] = 0.f;
        }
        #pragma unroll
        for (int nt = 0; nt < 8; nt++) {
            const int j = nt * 8 + gr;
            #pragma unroll
            for (int kk = 0; kk < 4; kk++) {
                const int c0 = kk * 16 + 2 * gc;
                unsigned b0 = h2u(__halves2half2(Ks[(c0    ) * KV_STRIDE + j],
                                                 Ks[(c0 + 1) * KV_STRIDE + j]));
                unsigned b1 = h2u(__halves2half2(Ks[(c0 + 8) * KV_STRIDE + j],
                                                 Ks[(c0 + 9) * KV_STRIDE + j]));
                mma_f16(S[nt], Aq[kk], b0, b1);
            }
        }

        // ---- base-2 online softmax (rows gr, gr+8) ----
        float mx0 = -CUDART_INF_F, mx1 = -CUDART_INF_F;
        #pragma unroll
        for (int nt = 0; nt < 8; nt++) {
            mx0 = fmaxf(mx0, fmaxf(S[nt][0], S[nt][1]));
            mx1 = fmaxf(mx1, fmaxf(S[nt][2], S[nt][3]));
        }
        mx0 = fmaxf(mx0, __shfl_xor_sync(0xffffffffu, mx0, 1));
        mx0 = fmaxf(mx0, __shfl_xor_sync(0xffffffffu, mx0, 2));
        mx1 = fmaxf(mx1, __shfl_xor_sync(0xffffffffu, mx1, 1));
        mx1 = fmaxf(mx1, __shfl_xor_sync(0xffffffffu, mx1, 2));

        const float mn0 = fmaxf(m0, mx0);
        const float mn1 = fmaxf(m1, mx1);
        const float al0 = ex2f(m0 - mn0);
        const float al1 = ex2f(m1 - mn1);
        float s0 = 0.f, s1 = 0.f;
        #pragma unroll
        for (int nt = 0; nt < 8; nt++) {
            float p0 = ex2f(S[nt][0] - mn0);
            float p1 = ex2f(S[nt][1] - mn0);
            float p2 = ex2f(S[nt][2] - mn1);
            float p3 = ex2f(S[nt][3] - mn1);
            S[nt][0] = p0; S[nt][1] = p1; S[nt][2] = p2; S[nt][3] = p3;
            s0 += p0 + p1; s1 += p2 + p3;
        }
        s0 += __shfl_xor_sync(0xffffffffu, s0, 1);
        s0 += __shfl_xor_sync(0xffffffffu, s0, 2);
        s1 += __shfl_xor_sync(0xffffffffu, s1, 1);
        s1 += __shfl_xor_sync(0xffffffffu, s1, 2);
        l0 = l0 * al0 + s0;  m0 = mn0;
        l1 = l1 * al1 + s1;  m1 = mn1;

        #pragma unroll
        for (int ct = 0; ct < 8; ct++) {
            Oacc[ct][0] *= al0; Oacc[ct][1] *= al0;
            Oacc[ct][2] *= al1; Oacc[ct][3] *= al1;
        }

        // ---- O += P V^T ; P A-fragments built in registers from S ----
        #pragma unroll
        for (int kk = 0; kk < 4; kk++) {
            unsigned pa[4];
            pa[0] = h2u(__floats2half2_rn(S[2*kk  ][0], S[2*kk  ][1]));
            pa[1] = h2u(__floats2half2_rn(S[2*kk  ][2], S[2*kk  ][3]));
            pa[2] = h2u(__floats2half2_rn(S[2*kk+1][0], S[2*kk+1][1]));
            pa[3] = h2u(__floats2half2_rn(S[2*kk+1][2], S[2*kk+1][3]));
            const int jb = kk * 16 + 2 * gc;
            #pragma unroll
            for (int ct = 0; ct < 8; ct++) {
                const int c = ct * 8 + gr;
                unsigned b0 = *reinterpret_cast<const unsigned*>(&Vs[c * KV_STRIDE + jb]);
                unsigned b1 = *reinterpret_cast<const unsigned*>(&Vs[c * KV_STRIDE + jb + 8]);
                mma_f16(Oacc[ct], pa, b0, b1);
            }
        }
    }

    // ---- epilogue: normalize and write O [d][seq] ----
    const float inv0 = 1.f / l0;
    const float inv1 = 1.f / l1;
    float* Og = g_obuf + ((size_t)b * CCH + h * DH) * HW;
    #pragma unroll
    for (int ct = 0; ct < 8; ct++) {
        const int c = ct * 8 + 2 * gc;
        Og[(size_t)(c    ) * HW + iw + gr    ] = Oacc[ct][0] * inv0;
        Og[(size_t)(c + 1) * HW + iw + gr    ] = Oacc[ct][1] * inv0;
        Og[(size_t)(c    ) * HW + iw + gr + 8] = Oacc[ct][2] * inv1;
        Og[(size_t)(c + 1) * HW + iw + gr + 8] = Oacc[ct][3] * inv1;
    }
}

// ---------------------------------------------------------------------------
extern "C" void kernel_launch(void* const* d_in, const int* in_sizes, int n_in,
                              void* d_out, int out_size) {
    const float* x      = (const float*)d_in[0];
    const float* norm_w = (const float*)d_in[1];
    const float* norm_b = (const float*)d_in[2];
    const float* qkv_w  = (const float*)d_in[3];
    const float* qkv_b  = (const float*)d_in[4];
    const float* proj_w = (const float*)d_in[5];
    const float* proj_b = (const float*)d_in[6];
    float* out = (float*)d_out;

    k_stats<<<32, 256>>>(x);
    k_coef<<<4, 256>>>(norm_w, norm_b);
    k_gemm<0><<<dim3(HW/64, 768/64, BB), 256>>>(qkv_w, x, qkv_b, nullptr, nullptr);
    k_attn<<<dim3(HW/128, BB*NH), 256>>>();
    k_gemm<1><<<dim3(HW/64, CCH/64, BB), 256>>>(proj_w, nullptr, proj_b, x, out);
}

// round 5
// speedup vs baseline: 4.8668x; 1.2005x over previous
#include <cuda_runtime.h>
#include <cuda_fp16.h>
#include <math_constants.h>
#include <cstddef>

// Problem constants
#define BB   4
#define CCH  256
#define NH   4
#define DH   64
#define GRP  8
#define HW   4096   // 64*64

// Scratch (device globals — no allocation allowed)
__device__ float g_qkv [(size_t)BB * 3 * CCH * HW];   // 48 MB  [b][768][4096]
__device__ float g_obuf[(size_t)BB * CCH * HW];       // 16 MB  [b][256][4096]
__device__ float g_mean[BB * GRP];
__device__ float g_rstd[BB * GRP];
__device__ float g_acoef[BB * CCH];
__device__ float g_bcoef[BB * CCH];

// ---------------------------------------------------------------------------
// Kernel 1: per-(batch, group) mean / rstd
// ---------------------------------------------------------------------------
__global__ void k_stats(const float* __restrict__ x) {
    const int bid = blockIdx.x;                        // 0..31 = b*8+g
    const float4* p = reinterpret_cast<const float4*>(x + (size_t)bid * 131072);
    float s = 0.f, s2 = 0.f;
    for (int i = threadIdx.x; i < 32768; i += 256) {
        float4 v = p[i];
        s  += v.x + v.y + v.z + v.w;
        s2 += v.x*v.x + v.y*v.y + v.z*v.z + v.w*v.w;
    }
    __shared__ float rs[256], rs2[256];
    rs[threadIdx.x] = s; rs2[threadIdx.x] = s2;
    __syncthreads();
    for (int off = 128; off > 0; off >>= 1) {
        if (threadIdx.x < off) {
            rs[threadIdx.x]  += rs[threadIdx.x + off];
            rs2[threadIdx.x] += rs2[threadIdx.x + off];
        }
        __syncthreads();
    }
    if (threadIdx.x == 0) {
        float mean = rs[0] * (1.f / 131072.f);
        float var  = rs2[0] * (1.f / 131072.f) - mean * mean;
        g_mean[bid] = mean;
        g_rstd[bid] = rsqrtf(var + 1e-5f);
    }
}

// ---------------------------------------------------------------------------
// Kernel 2: fold GroupNorm into per-(b,c) affine: h = x*a + bc
// ---------------------------------------------------------------------------
__global__ void k_coef(const float* __restrict__ nw, const float* __restrict__ nb) {
    int t = blockIdx.x * 256 + threadIdx.x;
    if (t >= BB * CCH) return;
    int b = t >> 8, c = t & 255;
    int gidx = b * GRP + (c >> 5);
    float a = nw[c] * g_rstd[gidx];
    g_acoef[t] = a;
    g_bcoef[t] = nb[c] - g_mean[gidx] * a;
}

// ---------------------------------------------------------------------------
// Kernel 3/5: tiled fp32 GEMM, 128x128 tile, 8x8 per thread, k-chunk 16.
//   out[b][m][n] = sum_k W[m][k] * B[b][k][n] (+bias) (+resid)
// ---------------------------------------------------------------------------
template<int MODE>
__global__ void __launch_bounds__(256, 2)
k_gemm(const float* __restrict__ W,
       const float* __restrict__ Bsrc,
       const float* __restrict__ bias,
       const float* __restrict__ resid,
       float* __restrict__ outp)
{
    __shared__ float As[16][132];   // [k][m]
    __shared__ float Bs[16][132];   // [k][n]
    const int t  = threadIdx.x;
    const int n0 = blockIdx.x * 128;
    const int m0 = blockIdx.y * 128;
    const int b  = blockIdx.z;
    const int r  = t >> 4;          // 0..15 -> m sub-block r*8
    const int q  = t & 15;          // 0..15 -> n sub-block q*8
    const int Mtot = (MODE == 0) ? 768 : 256;

    float acc[8][8];
    #pragma unroll
    for (int i = 0; i < 8; i++)
        #pragma unroll
        for (int j = 0; j < 8; j++) acc[i][j] = 0.f;

    for (int kk = 0; kk < 256; kk += 16) {
        #pragma unroll
        for (int l = 0; l < 2; l++) {
            const int idx = l * 256 + t;
            // A tile: 128m x 16k, load float4 along k, store transposed
            {
                const int m  = idx >> 2;
                const int kv = (idx & 3) * 4;
                float4 av = *reinterpret_cast<const float4*>(
                    &W[(size_t)(m0 + m) * 256 + kk + kv]);
                As[kv + 0][m] = av.x; As[kv + 1][m] = av.y;
                As[kv + 2][m] = av.z; As[kv + 3][m] = av.w;
            }
            // B tile: 16k x 128n, natural layout
            {
                const int k  = idx >> 5;
                const int nv = (idx & 31) * 4;
                const int ch = kk + k;
                float4 bv;
                if (MODE == 0) {
                    bv = *reinterpret_cast<const float4*>(
                        &Bsrc[((size_t)b * CCH + ch) * HW + n0 + nv]);
                    const float a  = g_acoef[b * CCH + ch];
                    const float bc = g_bcoef[b * CCH + ch];
                    bv.x = fmaf(bv.x, a, bc); bv.y = fmaf(bv.y, a, bc);
                    bv.z = fmaf(bv.z, a, bc); bv.w = fmaf(bv.w, a, bc);
                } else {
                    bv = *reinterpret_cast<const float4*>(
                        &g_obuf[((size_t)b * CCH + ch) * HW + n0 + nv]);
                }
                *reinterpret_cast<float4*>(&Bs[k][nv]) = bv;
            }
        }
        __syncthreads();

        #pragma unroll
        for (int kc = 0; kc < 16; kc++) {
            float a[8], bb[8];
            *reinterpret_cast<float4*>(a)      = *reinterpret_cast<const float4*>(&As[kc][r * 8]);
            *reinterpret_cast<float4*>(a + 4)  = *reinterpret_cast<const float4*>(&As[kc][r * 8 + 4]);
            *reinterpret_cast<float4*>(bb)     = *reinterpret_cast<const float4*>(&Bs[kc][q * 8]);
            *reinterpret_cast<float4*>(bb + 4) = *reinterpret_cast<const float4*>(&Bs[kc][q * 8 + 4]);
            #pragma unroll
            for (int i = 0; i < 8; i++)
                #pragma unroll
                for (int j = 0; j < 8; j++)
                    acc[i][j] = fmaf(a[i], bb[j], acc[i][j]);
        }
        __syncthreads();
    }

    #pragma unroll
    for (int mi = 0; mi < 8; mi++) {
        const int m = m0 + r * 8 + mi;
        const float bsv = bias[m];
        const size_t off = ((size_t)b * Mtot + m) * HW + n0 + q * 8;
        float4 v0, v1;
        v0.x = acc[mi][0] + bsv; v0.y = acc[mi][1] + bsv;
        v0.z = acc[mi][2] + bsv; v0.w = acc[mi][3] + bsv;
        v1.x = acc[mi][4] + bsv; v1.y = acc[mi][5] + bsv;
        v1.z = acc[mi][6] + bsv; v1.w = acc[mi][7] + bsv;
        if (MODE == 0) {
            *reinterpret_cast<float4*>(&g_qkv[off])     = v0;
            *reinterpret_cast<float4*>(&g_qkv[off + 4]) = v1;
        } else {
            float4 x0 = *reinterpret_cast<const float4*>(&resid[off]);
            float4 x1 = *reinterpret_cast<const float4*>(&resid[off + 4]);
            v0.x += x0.x; v0.y += x0.y; v0.z += x0.z; v0.w += x0.w;
            v1.x += x1.x; v1.y += x1.y; v1.z += x1.z; v1.w += x1.w;
            *reinterpret_cast<float4*>(&outp[off])     = v0;
            *reinterpret_cast<float4*>(&outp[off + 4]) = v1;
        }
    }
}

// ---------------------------------------------------------------------------
// Kernel 4: flash attention, fp16 mma m16n8k16 + ldmatrix fragment loads.
// Br=128 (8 warps x 16 rows), Bc=64, 64 KV tiles, base-2 online softmax.
// K/V smem: half [c=64][j=64], stride 72 halves (144 B, 16B-aligned rows).
//   S-phase B-frag: ldmatrix.x4.trans  ([k=c][n=j] row-major storage)
//   PV-phase B-frag: ldmatrix.x4       ([n=c][k=j] row-major storage)
// ---------------------------------------------------------------------------
#define KV_STRIDE 72
#define KV_ROWB   144   // bytes per smem row

__device__ __forceinline__ float ex2f(float x) {
    float y;
    asm("ex2.approx.f32 %0, %1;" : "=f"(y) : "f"(x));
    return y;
}

__device__ __forceinline__ unsigned h2u(__half2 h) {
    return *reinterpret_cast<unsigned*>(&h);
}

__device__ __forceinline__ void mma_f16(float c[4], const unsigned a[4],
                                        unsigned b0, unsigned b1) {
    asm volatile(
        "mma.sync.aligned.m16n8k16.row.col.f32.f16.f16.f32 "
        "{%0,%1,%2,%3}, {%4,%5,%6,%7}, {%8,%9}, {%0,%1,%2,%3};"
        : "+f"(c[0]), "+f"(c[1]), "+f"(c[2]), "+f"(c[3])
        : "r"(a[0]), "r"(a[1]), "r"(a[2]), "r"(a[3]), "r"(b0), "r"(b1));
}

__device__ __forceinline__ void ldmx4_t(unsigned r[4], unsigned addr) {
    asm volatile("ldmatrix.sync.aligned.m8n8.x4.trans.shared.b16 {%0,%1,%2,%3}, [%4];"
        : "=r"(r[0]), "=r"(r[1]), "=r"(r[2]), "=r"(r[3]) : "r"(addr));
}

__device__ __forceinline__ void ldmx4(unsigned r[4], unsigned addr) {
    asm volatile("ldmatrix.sync.aligned.m8n8.x4.shared.b16 {%0,%1,%2,%3}, [%4];"
        : "=r"(r[0]), "=r"(r[1]), "=r"(r[2]), "=r"(r[3]) : "r"(addr));
}

__global__ void __launch_bounds__(256, 2) k_attn() {
    __shared__ __half Ks[64 * KV_STRIDE];
    __shared__ __half Vs[64 * KV_STRIDE];

    const int t    = threadIdx.x;
    const int w    = t >> 5;
    const int lane = t & 31;
    const int gr   = lane >> 2;   // 0..7
    const int gc   = lane & 3;    // 0..3

    const int bh = blockIdx.y;
    const int b  = bh >> 2, h = bh & 3;
    const int i0 = blockIdx.x * 128;
    const int iw = i0 + w * 16;   // this warp's first query row

    const float* Qg = g_qkv + ((size_t)b * 768 +       h * DH) * HW;
    const float* Kg = g_qkv + ((size_t)b * 768 + 256 + h * DH) * HW;
    const float* Vg = g_qkv + ((size_t)b * 768 + 512 + h * DH) * HW;

    const unsigned ks_u32 = (unsigned)__cvta_generic_to_shared(Ks);
    const unsigned vs_u32 = (unsigned)__cvta_generic_to_shared(Vs);
    // K trans-ldmatrix: addr = ks + (p*32 + lane)*144 + nt*16
    const unsigned kA = ks_u32 + lane * KV_ROWB;
    // V ldmatrix: rows (ct + lane/16)*8 + lane%8, j-offset (2kk + (lane/8)%2)*8
    const unsigned vrow  = (lane >> 4) * 8 + (lane & 7);
    const unsigned vA = vs_u32 + vrow * KV_ROWB + ((lane >> 3) & 1) * 16;

    // Q A-fragments (scale * log2(e) folded in; softmax done base-2)
    const float qscale = 0.125f * 1.44269504088896341f;
    unsigned Aq[4][4];
    #pragma unroll
    for (int kk = 0; kk < 4; kk++) {
        const int c0 = kk * 16 + 2 * gc;
        #pragma unroll
        for (int half8 = 0; half8 < 2; half8++) {   // cols +0 / +8
            const int c = c0 + half8 * 8;
            float qlo0 = Qg[(size_t)(c    ) * HW + iw + gr] * qscale;
            float qhi0 = Qg[(size_t)(c + 1) * HW + iw + gr] * qscale;
            float qlo1 = Qg[(size_t)(c    ) * HW + iw + gr + 8] * qscale;
            float qhi1 = Qg[(size_t)(c + 1) * HW + iw + gr + 8] * qscale;
            Aq[kk][half8 * 2 + 0] = h2u(__floats2half2_rn(qlo0, qhi0));
            Aq[kk][half8 * 2 + 1] = h2u(__floats2half2_rn(qlo1, qhi1));
        }
    }

    float Oacc[8][4];
    #pragma unroll
    for (int i = 0; i < 8; i++) {
        Oacc[i][0] = 0.f; Oacc[i][1] = 0.f; Oacc[i][2] = 0.f; Oacc[i][3] = 0.f;
    }
    float m0 = -CUDART_INF_F, m1 = -CUDART_INF_F;
    float l0 = 0.f, l1 = 0.f;

    for (int jt = 0; jt < 64; jt++) {
        const int j0 = jt * 64;
        __syncthreads();   // protect previous tile's reads

        // fill K/V tiles (half), coalesced float4 loads, uint2 stores
        #pragma unroll
        for (int l = 0; l < 4; l++) {
            const int idx = l * 256 + t;              // 0..1023
            const int c   = idx >> 4;                 // 0..63
            const int jv  = (idx & 15) * 4;           // 0..60
            float4 kv = *reinterpret_cast<const float4*>(&Kg[(size_t)c * HW + j0 + jv]);
            float4 vv = *reinterpret_cast<const float4*>(&Vg[(size_t)c * HW + j0 + jv]);
            uint2 kw = make_uint2(h2u(__floats2half2_rn(kv.x, kv.y)),
                                  h2u(__floats2half2_rn(kv.z, kv.w)));
            uint2 vw = make_uint2(h2u(__floats2half2_rn(vv.x, vv.y)),
                                  h2u(__floats2half2_rn(vv.z, vv.w)));
            *reinterpret_cast<uint2*>(&Ks[c * KV_STRIDE + jv]) = kw;
            *reinterpret_cast<uint2*>(&Vs[c * KV_STRIDE + jv]) = vw;
        }
        __syncthreads();

        // ---- S = Q K^T [16 x 64] per warp; K frags via ldmatrix.trans ----
        float S[8][4];
        #pragma unroll
        for (int nt = 0; nt < 8; nt++) {
            S[nt][0] = 0.f; S[nt][1] = 0.f; S[nt][2] = 0.f; S[nt][3] = 0.f;
        }
        #pragma unroll
        for (int nt = 0; nt < 8; nt++) {
            unsigned kb[4];
            ldmx4_t(kb, kA + nt * 16);                 // c-blocks 0..3  (kk 0,1)
            mma_f16(S[nt], Aq[0], kb[0], kb[1]);
            mma_f16(S[nt], Aq[1], kb[2], kb[3]);
            ldmx4_t(kb, kA + 32 * KV_ROWB + nt * 16);  // c-blocks 4..7  (kk 2,3)
            mma_f16(S[nt], Aq[2], kb[0], kb[1]);
            mma_f16(S[nt], Aq[3], kb[2], kb[3]);
        }

        // ---- base-2 online softmax (rows gr, gr+8) ----
        float mx0 = -CUDART_INF_F, mx1 = -CUDART_INF_F;
        #pragma unroll
        for (int nt = 0; nt < 8; nt++) {
            mx0 = fmaxf(mx0, fmaxf(S[nt][0], S[nt][1]));
            mx1 = fmaxf(mx1, fmaxf(S[nt][2], S[nt][3]));
        }
        mx0 = fmaxf(mx0, __shfl_xor_sync(0xffffffffu, mx0, 1));
        mx0 = fmaxf(mx0, __shfl_xor_sync(0xffffffffu, mx0, 2));
        mx1 = fmaxf(mx1, __shfl_xor_sync(0xffffffffu, mx1, 1));
        mx1 = fmaxf(mx1, __shfl_xor_sync(0xffffffffu, mx1, 2));

        const float mn0 = fmaxf(m0, mx0);
        const float mn1 = fmaxf(m1, mx1);
        const float al0 = ex2f(m0 - mn0);
        const float al1 = ex2f(m1 - mn1);
        float s0 = 0.f, s1 = 0.f;
        #pragma unroll
        for (int nt = 0; nt < 8; nt++) {
            float p0 = ex2f(S[nt][0] - mn0);
            float p1 = ex2f(S[nt][1] - mn0);
            float p2 = ex2f(S[nt][2] - mn1);
            float p3 = ex2f(S[nt][3] - mn1);
            S[nt][0] = p0; S[nt][1] = p1; S[nt][2] = p2; S[nt][3] = p3;
            s0 += p0 + p1; s1 += p2 + p3;
        }
        s0 += __shfl_xor_sync(0xffffffffu, s0, 1);
        s0 += __shfl_xor_sync(0xffffffffu, s0, 2);
        s1 += __shfl_xor_sync(0xffffffffu, s1, 1);
        s1 += __shfl_xor_sync(0xffffffffu, s1, 2);
        l0 = l0 * al0 + s0;  m0 = mn0;
        l1 = l1 * al1 + s1;  m1 = mn1;

        #pragma unroll
        for (int ct = 0; ct < 8; ct++) {
            Oacc[ct][0] *= al0; Oacc[ct][1] *= al0;
            Oacc[ct][2] *= al1; Oacc[ct][3] *= al1;
        }

        // ---- O += P V^T ; P A-frags from registers, V B-frags via ldmatrix ----
        #pragma unroll
        for (int kk = 0; kk < 4; kk++) {
            unsigned pa[4];
            pa[0] = h2u(__floats2half2_rn(S[2*kk  ][0], S[2*kk  ][1]));
            pa[1] = h2u(__floats2half2_rn(S[2*kk  ][2], S[2*kk  ][3]));
            pa[2] = h2u(__floats2half2_rn(S[2*kk+1][0], S[2*kk+1][1]));
            pa[3] = h2u(__floats2half2_rn(S[2*kk+1][2], S[2*kk+1][3]));
            #pragma unroll
            for (int ct = 0; ct < 8; ct += 2) {
                unsigned vb[4];
                ldmx4(vb, vA + ct * (8 * KV_ROWB) + kk * 32);
                mma_f16(Oacc[ct    ], pa, vb[0], vb[1]);
                mma_f16(Oacc[ct + 1], pa, vb[2], vb[3]);
            }
        }
    }

    // ---- epilogue: normalize and write O [d][seq] ----
    const float inv0 = 1.f / l0;
    const float inv1 = 1.f / l1;
    float* Og = g_obuf + ((size_t)b * CCH + h * DH) * HW;
    #pragma unroll
    for (int ct = 0; ct < 8; ct++) {
        const int c = ct * 8 + 2 * gc;
        Og[(size_t)(c    ) * HW + iw + gr    ] = Oacc[ct][0] * inv0;
        Og[(size_t)(c + 1) * HW + iw + gr    ] = Oacc[ct][1] * inv0;
        Og[(size_t)(c    ) * HW + iw + gr + 8] = Oacc[ct][2] * inv1;
        Og[(size_t)(c + 1) * HW + iw + gr + 8] = Oacc[ct][3] * inv1;
    }
}

// ---------------------------------------------------------------------------
extern "C" void kernel_launch(void* const* d_in, const int* in_sizes, int n_in,
                              void* d_out, int out_size) {
    const float* x      = (const float*)d_in[0];
    const float* norm_w = (const float*)d_in[1];
    const float* norm_b = (const float*)d_in[2];
    const float* qkv_w  = (const float*)d_in[3];
    const float* qkv_b  = (const float*)d_in[4];
    const float* proj_w = (const float*)d_in[5];
    const float* proj_b = (const float*)d_in[6];
    float* out = (float*)d_out;

    k_stats<<<32, 256>>>(x);
    k_coef<<<4, 256>>>(norm_w, norm_b);
    k_gemm<0><<<dim3(HW/128, 768/128, BB), 256>>>(qkv_w, x, qkv_b, nullptr, nullptr);
    k_attn<<<dim3(HW/128, BB*NH), 256>>>();
    k_gemm<1><<<dim3(HW/128, CCH/128, BB), 256>>>(proj_w, nullptr, proj_b, x, out);
}

// round 6
// speedup vs baseline: 7.1072x; 1.4603x over previous
#include <cuda_runtime.h>
#include <cuda_fp16.h>
#include <math_constants.h>
#include <cstddef>

// Problem constants
#define BB   4
#define CCH  256
#define NH   4
#define DH   64
#define GRP  8
#define HW   4096   // 64*64

// Scratch (device globals — no allocation allowed)
__device__ float  g_q   [(size_t)BB * CCH * HW];      // fp32 Q   [b][256][4096]
__device__ __half g_kvh [(size_t)BB * 2 * CCH * HW];  // fp16 K,V [b][512][4096]
__device__ __half g_xh  [(size_t)BB * CCH * HW];      // fp16 normalized x
__device__ __half g_oh  [(size_t)BB * CCH * HW];      // fp16 attention out
__device__ float  g_obuf[(size_t)BB * CCH * HW];      // fp32 attention out
__device__ __half g_wqkvh[768 * 256];
__device__ __half g_wprojh[256 * 256];
__device__ float g_mean[BB * GRP];
__device__ float g_rstd[BB * GRP];
__device__ float g_acoef[BB * CCH];
__device__ float g_bcoef[BB * CCH];

// ---------------------------------------------------------------------------
// helpers
// ---------------------------------------------------------------------------
__device__ __forceinline__ float ex2f(float x) {
    float y; asm("ex2.approx.f32 %0, %1;" : "=f"(y) : "f"(x)); return y;
}
__device__ __forceinline__ unsigned h2u(__half2 h) {
    return *reinterpret_cast<unsigned*>(&h);
}
__device__ __forceinline__ void mma_f16(float c[4], const unsigned a[4],
                                        unsigned b0, unsigned b1) {
    asm volatile(
        "mma.sync.aligned.m16n8k16.row.col.f32.f16.f16.f32 "
        "{%0,%1,%2,%3}, {%4,%5,%6,%7}, {%8,%9}, {%0,%1,%2,%3};"
        : "+f"(c[0]), "+f"(c[1]), "+f"(c[2]), "+f"(c[3])
        : "r"(a[0]), "r"(a[1]), "r"(a[2]), "r"(a[3]), "r"(b0), "r"(b1));
}
__device__ __forceinline__ void ldmx4_t(unsigned r[4], unsigned addr) {
    asm volatile("ldmatrix.sync.aligned.m8n8.x4.trans.shared.b16 {%0,%1,%2,%3}, [%4];"
        : "=r"(r[0]), "=r"(r[1]), "=r"(r[2]), "=r"(r[3]) : "r"(addr));
}
__device__ __forceinline__ void ldmx4(unsigned r[4], unsigned addr) {
    asm volatile("ldmatrix.sync.aligned.m8n8.x4.shared.b16 {%0,%1,%2,%3}, [%4];"
        : "=r"(r[0]), "=r"(r[1]), "=r"(r[2]), "=r"(r[3]) : "r"(addr));
}
__device__ __forceinline__ void cpa16(unsigned dst, const void* src) {
    asm volatile("cp.async.cg.shared.global [%0], [%1], 16;" :: "r"(dst), "l"(src));
}
#define CP_COMMIT()  asm volatile("cp.async.commit_group;")
#define CP_WAIT(N)   asm volatile("cp.async.wait_group " #N ";")

// ---------------------------------------------------------------------------
// Kernel 1: per-(batch, group) mean / rstd
// ---------------------------------------------------------------------------
__global__ void k_stats(const float* __restrict__ x) {
    const int bid = blockIdx.x;
    const float4* p = reinterpret_cast<const float4*>(x + (size_t)bid * 131072);
    float s = 0.f, s2 = 0.f;
    for (int i = threadIdx.x; i < 32768; i += 256) {
        float4 v = p[i];
        s  += v.x + v.y + v.z + v.w;
        s2 += v.x*v.x + v.y*v.y + v.z*v.z + v.w*v.w;
    }
    __shared__ float rs[256], rs2[256];
    rs[threadIdx.x] = s; rs2[threadIdx.x] = s2;
    __syncthreads();
    for (int off = 128; off > 0; off >>= 1) {
        if (threadIdx.x < off) {
            rs[threadIdx.x]  += rs[threadIdx.x + off];
            rs2[threadIdx.x] += rs2[threadIdx.x + off];
        }
        __syncthreads();
    }
    if (threadIdx.x == 0) {
        float mean = rs[0] * (1.f / 131072.f);
        float var  = rs2[0] * (1.f / 131072.f) - mean * mean;
        g_mean[bid] = mean;
        g_rstd[bid] = rsqrtf(var + 1e-5f);
    }
}

// ---------------------------------------------------------------------------
// Kernel 2: per-(b,c) affine coefficients
// ---------------------------------------------------------------------------
__global__ void k_coef(const float* __restrict__ nw, const float* __restrict__ nb) {
    int t = blockIdx.x * 256 + threadIdx.x;
    if (t >= BB * CCH) return;
    int b = t >> 8, c = t & 255;
    int gidx = b * GRP + (c >> 5);
    float a = nw[c] * g_rstd[gidx];
    g_acoef[t] = a;
    g_bcoef[t] = nb[c] - g_mean[gidx] * a;
}

// ---------------------------------------------------------------------------
// Kernel 2b: convert weights to fp16
// ---------------------------------------------------------------------------
__global__ void k_wconv(const float* __restrict__ qkv_w,
                        const float* __restrict__ proj_w) {
    int i = blockIdx.x * 256 + threadIdx.x;       // 0..262143
    if (i < 768 * 256) g_wqkvh[i] = __float2half(qkv_w[i]);
    else               g_wprojh[i - 768 * 256] = __float2half(proj_w[i - 768 * 256]);
}

// ---------------------------------------------------------------------------
// Kernel 2c: g_xh = fp16( x * a + bc )
// ---------------------------------------------------------------------------
__global__ void k_xh(const float* __restrict__ x) {
    int id = blockIdx.x * 256 + threadIdx.x;      // over 2M float2
    int bc = id >> 11;                            // (b,c) index
    float a = g_acoef[bc], bb = g_bcoef[bc];
    float2 v = reinterpret_cast<const float2*>(x)[id];
    reinterpret_cast<__half2*>(g_xh)[id] =
        __floats2half2_rn(fmaf(v.x, a, bb), fmaf(v.y, a, bb));
}

// ---------------------------------------------------------------------------
// Kernel 4b: g_oh = fp16(g_obuf)
// ---------------------------------------------------------------------------
__global__ void k_cvt() {
    int id = blockIdx.x * 256 + threadIdx.x;      // over 2M float2
    float2 v = reinterpret_cast<const float2*>(g_obuf)[id];
    reinterpret_cast<__half2*>(g_oh)[id] = __floats2half2_rn(v.x, v.y);
}

// ---------------------------------------------------------------------------
// Kernel 3/5: fp16 tensor-core GEMM, 128x128 CTA tile, 32x64 warp tile.
//   out[b][m][n] = sum_k Wh[m][k] * Xh[b][k][n] (+bias) (+resid)
// MODE 0: W=g_wqkvh, X=g_xh; m<256 -> fp32 g_q, else fp16 g_kvh.
// MODE 1: W=g_wprojh, X=g_oh;  out = fp32 d_out + bias + residual x.
// K=256, kc=32 per stage, cp.async double-buffered.
// ---------------------------------------------------------------------------
#define AS_STRIDE 40    // halves per A smem row (80 B)
#define BS_STRIDE 136   // halves per B smem row (272 B)
#define AS_STAGE  (128 * AS_STRIDE)   // halves
#define BS_STAGE  (32 * BS_STRIDE)

template<int MODE>
__global__ void __launch_bounds__(256, 2)
k_gemm_h(const float* __restrict__ bias,
         const float* __restrict__ resid,
         float* __restrict__ outp)
{
    __shared__ __half As[2 * AS_STAGE];
    __shared__ __half Bs[2 * BS_STAGE];

    const int t = threadIdx.x;
    const int w = t >> 5, lane = t & 31;
    const int gr = lane >> 2, gc = lane & 3;
    const int n0 = blockIdx.x * 128;
    const int m0 = blockIdx.y * 128;
    const int b  = blockIdx.z;
    const int mw = (w & 3) * 32;
    const int nw = (w >> 2) * 64;

    const __half* Wh = (MODE == 0) ? g_wqkvh : g_wprojh;
    const __half* Xh = (MODE == 0) ? g_xh    : g_oh;

    const unsigned as_u = (unsigned)__cvta_generic_to_shared(As);
    const unsigned bs_u = (unsigned)__cvta_generic_to_shared(Bs);

    // fill ids
    const int ar = t >> 1;              // A row 0..127
    const int ac = (t & 1) * 2;         // A chunk base 0 or 2 (each thread 2 chunks)
    const int br = t >> 3;              // B row 0..31
    const int bcw = (t & 7) * 2;        // B chunk base (each thread 2 chunks)

    float acc[2][8][4];
    #pragma unroll
    for (int mt = 0; mt < 2; mt++)
        #pragma unroll
        for (int nt = 0; nt < 8; nt++) {
            acc[mt][nt][0] = 0.f; acc[mt][nt][1] = 0.f;
            acc[mt][nt][2] = 0.f; acc[mt][nt][3] = 0.f;
        }

    // prefetch chunk 0
    {
        const int kk = 0;
        cpa16(as_u + ar * 80 + (ac    ) * 16, Wh + (size_t)(m0 + ar) * 256 + kk + (ac    ) * 8);
        cpa16(as_u + ar * 80 + (ac + 1) * 16, Wh + (size_t)(m0 + ar) * 256 + kk + (ac + 1) * 8);
        cpa16(bs_u + br * 272 + (bcw    ) * 16, Xh + ((size_t)b * CCH + kk + br) * HW + n0 + (bcw    ) * 8);
        cpa16(bs_u + br * 272 + (bcw + 1) * 16, Xh + ((size_t)b * CCH + kk + br) * HW + n0 + (bcw + 1) * 8);
        CP_COMMIT();
    }

    #pragma unroll
    for (int c = 0; c < 8; c++) {
        if (c < 7) {
            const int kk = (c + 1) * 32;
            const unsigned sa = ((c + 1) & 1) * (AS_STAGE * 2);
            const unsigned sb = ((c + 1) & 1) * (BS_STAGE * 2);
            cpa16(as_u + sa + ar * 80 + (ac    ) * 16, Wh + (size_t)(m0 + ar) * 256 + kk + (ac    ) * 8);
            cpa16(as_u + sa + ar * 80 + (ac + 1) * 16, Wh + (size_t)(m0 + ar) * 256 + kk + (ac + 1) * 8);
            cpa16(bs_u + sb + br * 272 + (bcw    ) * 16, Xh + ((size_t)b * CCH + kk + br) * HW + n0 + (bcw    ) * 8);
            cpa16(bs_u + sb + br * 272 + (bcw + 1) * 16, Xh + ((size_t)b * CCH + kk + br) * HW + n0 + (bcw + 1) * 8);
            CP_COMMIT();
            CP_WAIT(1);
        } else {
            CP_WAIT(0);
        }
        __syncthreads();

        const unsigned abase = as_u + (c & 1) * (AS_STAGE * 2);
        const unsigned bbase = bs_u + (c & 1) * (BS_STAGE * 2);

        unsigned a[2][2][4];
        #pragma unroll
        for (int mt = 0; mt < 2; mt++)
            #pragma unroll
            for (int kq = 0; kq < 2; kq++)
                ldmx4(a[mt][kq], abase + (mw + mt * 16 + (lane & 15)) * 80
                                  + kq * 32 + (lane >> 4) * 16);

        #pragma unroll
        for (int nt = 0; nt < 8; nt++) {
            unsigned bb[4];
            ldmx4_t(bb, bbase + lane * 272 + (nw + nt * 8) * 2);
            #pragma unroll
            for (int mt = 0; mt < 2; mt++) {
                mma_f16(acc[mt][nt], a[mt][0], bb[0], bb[1]);
                mma_f16(acc[mt][nt], a[mt][1], bb[2], bb[3]);
            }
        }
        __syncthreads();
    }

    // ---- epilogue ----
    #pragma unroll
    for (int mt = 0; mt < 2; mt++) {
        const int mA = m0 + mw + mt * 16 + gr;       // row for regs 0,1
        const int mB = mA + 8;                        // row for regs 2,3
        const float bA = bias[mA], bBv = bias[mB];
        #pragma unroll
        for (int nt = 0; nt < 8; nt++) {
            const int n = n0 + nw + nt * 8 + 2 * gc;
            float v0 = acc[mt][nt][0] + bA, v1 = acc[mt][nt][1] + bA;
            float v2 = acc[mt][nt][2] + bBv, v3 = acc[mt][nt][3] + bBv;
            if (MODE == 0) {
                if (m0 < 256) {
                    *reinterpret_cast<float2*>(&g_q[((size_t)b * CCH + mA) * HW + n]) = make_float2(v0, v1);
                    *reinterpret_cast<float2*>(&g_q[((size_t)b * CCH + mB) * HW + n]) = make_float2(v2, v3);
                } else {
                    const int ka = mA - 256, kb2 = mB - 256;
                    *reinterpret_cast<__half2*>(&g_kvh[((size_t)b * 512 + ka) * HW + n]) = __floats2half2_rn(v0, v1);
                    *reinterpret_cast<__half2*>(&g_kvh[((size_t)b * 512 + kb2) * HW + n]) = __floats2half2_rn(v2, v3);
                }
            } else {
                const size_t oA = ((size_t)b * CCH + mA) * HW + n;
                const size_t oB = ((size_t)b * CCH + mB) * HW + n;
                float2 xA = *reinterpret_cast<const float2*>(&resid[oA]);
                float2 xB = *reinterpret_cast<const float2*>(&resid[oB]);
                *reinterpret_cast<float2*>(&outp[oA]) = make_float2(v0 + xA.x, v1 + xA.y);
                *reinterpret_cast<float2*>(&outp[oB]) = make_float2(v2 + xB.x, v3 + xB.y);
            }
        }
    }
}

// ---------------------------------------------------------------------------
// Kernel 4: flash attention, fp16 mma + ldmatrix + cp.async double buffer.
// Br=128 (8 warps x 16 rows), Bc=64, 64 KV tiles, base-2 online softmax.
// K/V now fp16 in global (g_kvh) -> fill is pure cp.async.
// smem per stage: Ks[64][72], Vs[64][72] half (stride 144 B).
// ---------------------------------------------------------------------------
#define KV_STRIDE 72
#define KV_ROWB   144
#define KV_STAGE  (64 * KV_STRIDE)    // halves per tensor per stage

__global__ void __launch_bounds__(256, 2) k_attn() {
    __shared__ __half Ks[2 * KV_STAGE];
    __shared__ __half Vs[2 * KV_STAGE];

    const int t    = threadIdx.x;
    const int w    = t >> 5;
    const int lane = t & 31;
    const int gr   = lane >> 2;
    const int gc   = lane & 3;

    const int bh = blockIdx.y;
    const int b  = bh >> 2, h = bh & 3;
    const int i0 = blockIdx.x * 128;
    const int iw = i0 + w * 16;

    const float*  Qg = g_q   + ((size_t)b * CCH + h * DH) * HW;
    const __half* Kg = g_kvh + ((size_t)b * 512 +       h * DH) * HW;
    const __half* Vg = g_kvh + ((size_t)b * 512 + 256 + h * DH) * HW;

    const unsigned ks_u = (unsigned)__cvta_generic_to_shared(Ks);
    const unsigned vs_u = (unsigned)__cvta_generic_to_shared(Vs);

    // fill ids: 512 chunks per tensor; thread does 2 K + 2 V
    const int fr = t >> 2;              // row 0..63
    const int fc = (t & 3) * 2;         // chunk base 0,2,4,6

    const unsigned vrow = (lane >> 4) * 8 + (lane & 7);
    const unsigned vAoff = vrow * KV_ROWB + ((lane >> 3) & 1) * 16;
    const unsigned kAoff = lane * KV_ROWB;

    // Q A-fragments (scale * log2(e) folded)
    const float qscale = 0.125f * 1.44269504088896341f;
    unsigned Aq[4][4];
    #pragma unroll
    for (int kk = 0; kk < 4; kk++) {
        const int c0 = kk * 16 + 2 * gc;
        #pragma unroll
        for (int half8 = 0; half8 < 2; half8++) {
            const int c = c0 + half8 * 8;
            float qlo0 = Qg[(size_t)(c    ) * HW + iw + gr] * qscale;
            float qhi0 = Qg[(size_t)(c + 1) * HW + iw + gr] * qscale;
            float qlo1 = Qg[(size_t)(c    ) * HW + iw + gr + 8] * qscale;
            float qhi1 = Qg[(size_t)(c + 1) * HW + iw + gr + 8] * qscale;
            Aq[kk][half8 * 2 + 0] = h2u(__floats2half2_rn(qlo0, qhi0));
            Aq[kk][half8 * 2 + 1] = h2u(__floats2half2_rn(qlo1, qhi1));
        }
    }

    float Oacc[8][4];
    #pragma unroll
    for (int i = 0; i < 8; i++) {
        Oacc[i][0] = 0.f; Oacc[i][1] = 0.f; Oacc[i][2] = 0.f; Oacc[i][3] = 0.f;
    }
    float m0 = -CUDART_INF_F, m1 = -CUDART_INF_F;
    float l0 = 0.f, l1 = 0.f;

    // prefetch tile 0 into stage 0
    {
        cpa16(ks_u + fr * KV_ROWB + (fc    ) * 16, Kg + (size_t)fr * HW + (fc    ) * 8);
        cpa16(ks_u + fr * KV_ROWB + (fc + 1) * 16, Kg + (size_t)fr * HW + (fc + 1) * 8);
        cpa16(vs_u + fr * KV_ROWB + (fc    ) * 16, Vg + (size_t)fr * HW + (fc    ) * 8);
        cpa16(vs_u + fr * KV_ROWB + (fc + 1) * 16, Vg + (size_t)fr * HW + (fc + 1) * 8);
        CP_COMMIT();
    }

    for (int jt = 0; jt < 64; jt++) {
        if (jt < 63) {
            const int j0 = (jt + 1) * 64;
            const unsigned s = ((jt + 1) & 1) * (KV_STAGE * 2);
            cpa16(ks_u + s + fr * KV_ROWB + (fc    ) * 16, Kg + (size_t)fr * HW + j0 + (fc    ) * 8);
            cpa16(ks_u + s + fr * KV_ROWB + (fc + 1) * 16, Kg + (size_t)fr * HW + j0 + (fc + 1) * 8);
            cpa16(vs_u + s + fr * KV_ROWB + (fc    ) * 16, Vg + (size_t)fr * HW + j0 + (fc    ) * 8);
            cpa16(vs_u + s + fr * KV_ROWB + (fc + 1) * 16, Vg + (size_t)fr * HW + j0 + (fc + 1) * 8);
            CP_COMMIT();
            CP_WAIT(1);
        } else {
            CP_WAIT(0);
        }
        __syncthreads();

        const unsigned soff = (jt & 1) * (KV_STAGE * 2);
        const unsigned kA = ks_u + soff + kAoff;
        const unsigned vA = vs_u + soff + vAoff;

        // ---- S = Q K^T ----
        float S[8][4];
        #pragma unroll
        for (int nt = 0; nt < 8; nt++) {
            S[nt][0] = 0.f; S[nt][1] = 0.f; S[nt][2] = 0.f; S[nt][3] = 0.f;
        }
        #pragma unroll
        for (int nt = 0; nt < 8; nt++) {
            unsigned kb[4];
            ldmx4_t(kb, kA + nt * 16);
            mma_f16(S[nt], Aq[0], kb[0], kb[1]);
            mma_f16(S[nt], Aq[1], kb[2], kb[3]);
            ldmx4_t(kb, kA + 32 * KV_ROWB + nt * 16);
            mma_f16(S[nt], Aq[2], kb[0], kb[1]);
            mma_f16(S[nt], Aq[3], kb[2], kb[3]);
        }

        // ---- base-2 online softmax ----
        float mx0 = -CUDART_INF_F, mx1 = -CUDART_INF_F;
        #pragma unroll
        for (int nt = 0; nt < 8; nt++) {
            mx0 = fmaxf(mx0, fmaxf(S[nt][0], S[nt][1]));
            mx1 = fmaxf(mx1, fmaxf(S[nt][2], S[nt][3]));
        }
        mx0 = fmaxf(mx0, __shfl_xor_sync(0xffffffffu, mx0, 1));
        mx0 = fmaxf(mx0, __shfl_xor_sync(0xffffffffu, mx0, 2));
        mx1 = fmaxf(mx1, __shfl_xor_sync(0xffffffffu, mx1, 1));
        mx1 = fmaxf(mx1, __shfl_xor_sync(0xffffffffu, mx1, 2));

        const float mn0 = fmaxf(m0, mx0);
        const float mn1 = fmaxf(m1, mx1);
        const float al0 = ex2f(m0 - mn0);
        const float al1 = ex2f(m1 - mn1);
        float s0 = 0.f, s1 = 0.f;
        #pragma unroll
        for (int nt = 0; nt < 8; nt++) {
            float p0 = ex2f(S[nt][0] - mn0);
            float p1 = ex2f(S[nt][1] - mn0);
            float p2 = ex2f(S[nt][2] - mn1);
            float p3 = ex2f(S[nt][3] - mn1);
            S[nt][0] = p0; S[nt][1] = p1; S[nt][2] = p2; S[nt][3] = p3;
            s0 += p0 + p1; s1 += p2 + p3;
        }
        s0 += __shfl_xor_sync(0xffffffffu, s0, 1);
        s0 += __shfl_xor_sync(0xffffffffu, s0, 2);
        s1 += __shfl_xor_sync(0xffffffffu, s1, 1);
        s1 += __shfl_xor_sync(0xffffffffu, s1, 2);
        l0 = l0 * al0 + s0;  m0 = mn0;
        l1 = l1 * al1 + s1;  m1 = mn1;

        #pragma unroll
        for (int ct = 0; ct < 8; ct++) {
            Oacc[ct][0] *= al0; Oacc[ct][1] *= al0;
            Oacc[ct][2] *= al1; Oacc[ct][3] *= al1;
        }

        // ---- O += P V^T ----
        #pragma unroll
        for (int kk = 0; kk < 4; kk++) {
            unsigned pa[4];
            pa[0] = h2u(__floats2half2_rn(S[2*kk  ][0], S[2*kk  ][1]));
            pa[1] = h2u(__floats2half2_rn(S[2*kk  ][2], S[2*kk  ][3]));
            pa[2] = h2u(__floats2half2_rn(S[2*kk+1][0], S[2*kk+1][1]));
            pa[3] = h2u(__floats2half2_rn(S[2*kk+1][2], S[2*kk+1][3]));
            #pragma unroll
            for (int ct = 0; ct < 8; ct += 2) {
                unsigned vb[4];
                ldmx4(vb, vA + ct * (8 * KV_ROWB) + kk * 32);
                mma_f16(Oacc[ct    ], pa, vb[0], vb[1]);
                mma_f16(Oacc[ct + 1], pa, vb[2], vb[3]);
            }
        }
        __syncthreads();
    }

    // ---- epilogue: normalize, write fp32 O ----
    const float inv0 = 1.f / l0;
    const float inv1 = 1.f / l1;
    float* Og = g_obuf + ((size_t)b * CCH + h * DH) * HW;
    #pragma unroll
    for (int ct = 0; ct < 8; ct++) {
        const int c = ct * 8 + 2 * gc;
        Og[(size_t)(c    ) * HW + iw + gr    ] = Oacc[ct][0] * inv0;
        Og[(size_t)(c + 1) * HW + iw + gr    ] = Oacc[ct][1] * inv0;
        Og[(size_t)(c    ) * HW + iw + gr + 8] = Oacc[ct][2] * inv1;
        Og[(size_t)(c + 1) * HW + iw + gr + 8] = Oacc[ct][3] * inv1;
    }
}

// ---------------------------------------------------------------------------
extern "C" void kernel_launch(void* const* d_in, const int* in_sizes, int n_in,
                              void* d_out, int out_size) {
    const float* x      = (const float*)d_in[0];
    const float* norm_w = (const float*)d_in[1];
    const float* norm_b = (const float*)d_in[2];
    const float* qkv_w  = (const float*)d_in[3];
    const float* qkv_b  = (const float*)d_in[4];
    const float* proj_w = (const float*)d_in[5];
    const float* proj_b = (const float*)d_in[6];
    float* out = (float*)d_out;

    k_stats<<<32, 256>>>(x);
    k_coef<<<4, 256>>>(norm_w, norm_b);
    k_wconv<<<1024, 256>>>(qkv_w, proj_w);
    k_xh<<<8192, 256>>>(x);
    k_gemm_h<0><<<dim3(32, 6, BB), 256>>>(qkv_b, nullptr, nullptr);
    k_attn<<<dim3(HW/128, BB*NH), 256>>>();
    k_cvt<<<8192, 256>>>();
    k_gemm_h<1><<<dim3(32, 2, BB), 256>>>(proj_b, x, out);
}

// round 7
// speedup vs baseline: 7.4654x; 1.0504x over previous
#include <cuda_runtime.h>
#include <cuda_fp16.h>
#include <math_constants.h>
#include <cstddef>

// Problem constants
#define BB   4
#define CCH  256
#define NH   4
#define DH   64
#define GRP  8
#define HW   4096   // 64*64

// Scratch (device globals — no allocation allowed)
__device__ __half g_qkvh[(size_t)BB * 3 * CCH * HW];  // fp16 Q(scaled),K,V [b][768][4096]
__device__ __half g_xh  [(size_t)BB * CCH * HW];      // fp16 normalized x
__device__ __half g_oh  [(size_t)BB * CCH * HW];      // fp16 attention out
__device__ __half g_wqkvh[768 * 256];
__device__ __half g_wprojh[256 * 256];
__device__ float2 g_part[256];                        // partial (sum, sumsq)
__device__ float g_acoef[BB * CCH];
__device__ float g_bcoef[BB * CCH];

// ---------------------------------------------------------------------------
// helpers
// ---------------------------------------------------------------------------
__device__ __forceinline__ float ex2f(float x) {
    float y; asm("ex2.approx.f32 %0, %1;" : "=f"(y) : "f"(x)); return y;
}
__device__ __forceinline__ unsigned h2u(__half2 h) {
    return *reinterpret_cast<unsigned*>(&h);
}
__device__ __forceinline__ void mma_f16(float c[4], const unsigned a[4],
                                        unsigned b0, unsigned b1) {
    asm volatile(
        "mma.sync.aligned.m16n8k16.row.col.f32.f16.f16.f32 "
        "{%0,%1,%2,%3}, {%4,%5,%6,%7}, {%8,%9}, {%0,%1,%2,%3};"
        : "+f"(c[0]), "+f"(c[1]), "+f"(c[2]), "+f"(c[3])
        : "r"(a[0]), "r"(a[1]), "r"(a[2]), "r"(a[3]), "r"(b0), "r"(b1));
}
__device__ __forceinline__ void ldmx4_t(unsigned r[4], unsigned addr) {
    asm volatile("ldmatrix.sync.aligned.m8n8.x4.trans.shared.b16 {%0,%1,%2,%3}, [%4];"
        : "=r"(r[0]), "=r"(r[1]), "=r"(r[2]), "=r"(r[3]) : "r"(addr));
}
__device__ __forceinline__ void ldmx4(unsigned r[4], unsigned addr) {
    asm volatile("ldmatrix.sync.aligned.m8n8.x4.shared.b16 {%0,%1,%2,%3}, [%4];"
        : "=r"(r[0]), "=r"(r[1]), "=r"(r[2]), "=r"(r[3]) : "r"(addr));
}
__device__ __forceinline__ void cpa16(unsigned dst, const void* src) {
    asm volatile("cp.async.cg.shared.global [%0], [%1], 16;" :: "r"(dst), "l"(src));
}
#define CP_COMMIT()  asm volatile("cp.async.commit_group;")
#define CP_WAIT(N)   asm volatile("cp.async.wait_group " #N ";")

// ---------------------------------------------------------------------------
// Kernel 1: partial sums, 256 blocks (8 per (b,g) group, each 16384 floats)
// ---------------------------------------------------------------------------
__global__ void k_stats(const float* __restrict__ x) {
    const int bid = blockIdx.x;
    const float4* p = reinterpret_cast<const float4*>(x + (size_t)bid * 16384);
    float s = 0.f, s2 = 0.f;
    for (int i = threadIdx.x; i < 4096; i += 256) {
        float4 v = p[i];
        s  += v.x + v.y + v.z + v.w;
        s2 += v.x*v.x + v.y*v.y + v.z*v.z + v.w*v.w;
    }
    __shared__ float rs[256], rs2[256];
    rs[threadIdx.x] = s; rs2[threadIdx.x] = s2;
    __syncthreads();
    for (int off = 128; off > 0; off >>= 1) {
        if (threadIdx.x < off) {
            rs[threadIdx.x]  += rs[threadIdx.x + off];
            rs2[threadIdx.x] += rs2[threadIdx.x + off];
        }
        __syncthreads();
    }
    if (threadIdx.x == 0) g_part[bid] = make_float2(rs[0], rs2[0]);
}

// ---------------------------------------------------------------------------
// Kernel 2: finalize stats + per-(b,c) affine coefficients
// ---------------------------------------------------------------------------
__global__ void k_coef(const float* __restrict__ nw, const float* __restrict__ nb) {
    int t = blockIdx.x * 256 + threadIdx.x;
    if (t >= BB * CCH) return;
    int b = t >> 8, c = t & 255;
    int gidx = b * GRP + (c >> 5);
    float s = 0.f, s2 = 0.f;
    #pragma unroll
    for (int i = 0; i < 8; i++) {
        float2 p = g_part[gidx * 8 + i];
        s += p.x; s2 += p.y;
    }
    float mean = s * (1.f / 131072.f);
    float var  = s2 * (1.f / 131072.f) - mean * mean;
    float rstd = rsqrtf(var + 1e-5f);
    float a = nw[c] * rstd;
    g_acoef[t] = a;
    g_bcoef[t] = nb[c] - mean * a;
}

// ---------------------------------------------------------------------------
// Kernel 2b: convert weights to fp16
// ---------------------------------------------------------------------------
__global__ void k_wconv(const float* __restrict__ qkv_w,
                        const float* __restrict__ proj_w) {
    int i = blockIdx.x * 256 + threadIdx.x;       // 0..262143
    if (i < 768 * 256) g_wqkvh[i] = __float2half(qkv_w[i]);
    else               g_wprojh[i - 768 * 256] = __float2half(proj_w[i - 768 * 256]);
}

// ---------------------------------------------------------------------------
// Kernel 2c: g_xh = fp16( x * a + bc ), float4 path
// ---------------------------------------------------------------------------
__global__ void k_xh(const float* __restrict__ x) {
    int id = blockIdx.x * 256 + threadIdx.x;      // over 1M float4
    int bc = id >> 10;                            // 1024 float4 per (b,c) row
    float a = g_acoef[bc], bb = g_bcoef[bc];
    float4 v = reinterpret_cast<const float4*>(x)[id];
    __half2 lo = __floats2half2_rn(fmaf(v.x, a, bb), fmaf(v.y, a, bb));
    __half2 hi = __floats2half2_rn(fmaf(v.z, a, bb), fmaf(v.w, a, bb));
    reinterpret_cast<uint2*>(g_xh)[id] = make_uint2(h2u(lo), h2u(hi));
}

// ---------------------------------------------------------------------------
// Kernel 3/5: fp16 tensor-core GEMM, 128x128 CTA tile, 32x64 warp tile.
// MODE 0: W=g_wqkvh, X=g_xh -> fp16 g_qkvh (Q rows pre-scaled by 0.125*log2e).
// MODE 1: W=g_wprojh, X=g_oh -> fp32 d_out + bias + residual x.
// ---------------------------------------------------------------------------
#define AS_STAGE  (128 * 40)   // halves (row stride 40 halves = 80 B)
#define BS_STAGE  (32 * 136)   // halves (row stride 136 halves = 272 B)
#define QSCALE 0.180336880111f  // 0.125 * log2(e)

template<int MODE>
__global__ void __launch_bounds__(256, 2)
k_gemm_h(const float* __restrict__ bias,
         const float* __restrict__ resid,
         float* __restrict__ outp)
{
    __shared__ __half As[2 * AS_STAGE];
    __shared__ __half Bs[2 * BS_STAGE];

    const int t = threadIdx.x;
    const int w = t >> 5, lane = t & 31;
    const int gr = lane >> 2, gc = lane & 3;
    const int n0 = blockIdx.x * 128;
    const int m0 = blockIdx.y * 128;
    const int b  = blockIdx.z;
    const int mw = (w & 3) * 32;
    const int nw = (w >> 2) * 64;

    const __half* Wh = (MODE == 0) ? g_wqkvh : g_wprojh;
    const __half* Xh = (MODE == 0) ? g_xh    : g_oh;

    const unsigned as_u = (unsigned)__cvta_generic_to_shared(As);
    const unsigned bs_u = (unsigned)__cvta_generic_to_shared(Bs);

    const int ar = t >> 1;
    const int ac = (t & 1) * 2;
    const int br = t >> 3;
    const int bcw = (t & 7) * 2;

    float acc[2][8][4];
    #pragma unroll
    for (int mt = 0; mt < 2; mt++)
        #pragma unroll
        for (int nt = 0; nt < 8; nt++) {
            acc[mt][nt][0] = 0.f; acc[mt][nt][1] = 0.f;
            acc[mt][nt][2] = 0.f; acc[mt][nt][3] = 0.f;
        }

    {
        cpa16(as_u + ar * 80 + (ac    ) * 16, Wh + (size_t)(m0 + ar) * 256 + (ac    ) * 8);
        cpa16(as_u + ar * 80 + (ac + 1) * 16, Wh + (size_t)(m0 + ar) * 256 + (ac + 1) * 8);
        cpa16(bs_u + br * 272 + (bcw    ) * 16, Xh + ((size_t)b * CCH + br) * HW + n0 + (bcw    ) * 8);
        cpa16(bs_u + br * 272 + (bcw + 1) * 16, Xh + ((size_t)b * CCH + br) * HW + n0 + (bcw + 1) * 8);
        CP_COMMIT();
    }

    #pragma unroll
    for (int c = 0; c < 8; c++) {
        if (c < 7) {
            const int kk = (c + 1) * 32;
            const unsigned sa = ((c + 1) & 1) * (AS_STAGE * 2);
            const unsigned sb = ((c + 1) & 1) * (BS_STAGE * 2);
            cpa16(as_u + sa + ar * 80 + (ac    ) * 16, Wh + (size_t)(m0 + ar) * 256 + kk + (ac    ) * 8);
            cpa16(as_u + sa + ar * 80 + (ac + 1) * 16, Wh + (size_t)(m0 + ar) * 256 + kk + (ac + 1) * 8);
            cpa16(bs_u + sb + br * 272 + (bcw    ) * 16, Xh + ((size_t)b * CCH + kk + br) * HW + n0 + (bcw    ) * 8);
            cpa16(bs_u + sb + br * 272 + (bcw + 1) * 16, Xh + ((size_t)b * CCH + kk + br) * HW + n0 + (bcw + 1) * 8);
            CP_COMMIT();
            CP_WAIT(1);
        } else {
            CP_WAIT(0);
        }
        __syncthreads();

        const unsigned abase = as_u + (c & 1) * (AS_STAGE * 2);
        const unsigned bbase = bs_u + (c & 1) * (BS_STAGE * 2);

        unsigned a[2][2][4];
        #pragma unroll
        for (int mt = 0; mt < 2; mt++)
            #pragma unroll
            for (int kq = 0; kq < 2; kq++)
                ldmx4(a[mt][kq], abase + (mw + mt * 16 + (lane & 15)) * 80
                                  + kq * 32 + (lane >> 4) * 16);

        #pragma unroll
        for (int nt = 0; nt < 8; nt++) {
            unsigned bb[4];
            ldmx4_t(bb, bbase + lane * 272 + (nw + nt * 8) * 2);
            #pragma unroll
            for (int mt = 0; mt < 2; mt++) {
                mma_f16(acc[mt][nt], a[mt][0], bb[0], bb[1]);
                mma_f16(acc[mt][nt], a[mt][1], bb[2], bb[3]);
            }
        }
        __syncthreads();
    }

    // ---- epilogue ----
    const float osc = (MODE == 0 && m0 < 256) ? QSCALE : 1.f;
    #pragma unroll
    for (int mt = 0; mt < 2; mt++) {
        const int mA = m0 + mw + mt * 16 + gr;
        const int mB = mA + 8;
        const float bA = bias[mA], bBv = bias[mB];
        #pragma unroll
        for (int nt = 0; nt < 8; nt++) {
            const int n = n0 + nw + nt * 8 + 2 * gc;
            float v0 = (acc[mt][nt][0] + bA) * osc, v1 = (acc[mt][nt][1] + bA) * osc;
            float v2 = (acc[mt][nt][2] + bBv) * osc, v3 = (acc[mt][nt][3] + bBv) * osc;
            if (MODE == 0) {
                *reinterpret_cast<__half2*>(&g_qkvh[((size_t)b * 768 + mA) * HW + n]) = __floats2half2_rn(v0, v1);
                *reinterpret_cast<__half2*>(&g_qkvh[((size_t)b * 768 + mB) * HW + n]) = __floats2half2_rn(v2, v3);
            } else {
                const size_t oA = ((size_t)b * CCH + mA) * HW + n;
                const size_t oB = ((size_t)b * CCH + mB) * HW + n;
                float2 xA = *reinterpret_cast<const float2*>(&resid[oA]);
                float2 xB = *reinterpret_cast<const float2*>(&resid[oB]);
                *reinterpret_cast<float2*>(&outp[oA]) = make_float2(v0 + xA.x, v1 + xA.y);
                *reinterpret_cast<float2*>(&outp[oB]) = make_float2(v2 + xB.x, v3 + xB.y);
            }
        }
    }
}

// ---------------------------------------------------------------------------
// Kernel 4: flash attention, fp16 mma + ldmatrix + 4-stage cp.async pipeline
// (prefetch distance 2 -> ONE __syncthreads per tile is race-free).
// Br=128 (8 warps x 16 rows), Bc=64, 64 tiles. Q pre-scaled fp16 in g_qkvh.
// Writes fp16 O directly to g_oh.
// ---------------------------------------------------------------------------
#define KV_STRIDE 72
#define KV_ROWB   144
#define KV_STAGE  (64 * KV_STRIDE)    // halves per tensor per stage
#define ATTN_SMEM (4 * KV_STAGE * 2 * 2)   // 4 stages x (K+V) x bytes

__global__ void __launch_bounds__(256, 2) k_attn() {
    extern __shared__ __half smem[];

    const int t    = threadIdx.x;
    const int w    = t >> 5;
    const int lane = t & 31;
    const int gr   = lane >> 2;
    const int gc   = lane & 3;

    const int bh = blockIdx.y;
    const int b  = bh >> 2, h = bh & 3;
    const int i0 = blockIdx.x * 128;
    const int iw = i0 + w * 16;

    const __half* Qg = g_qkvh + ((size_t)b * 768 +       h * DH) * HW;
    const __half* Kg = g_qkvh + ((size_t)b * 768 + 256 + h * DH) * HW;
    const __half* Vg = g_qkvh + ((size_t)b * 768 + 512 + h * DH) * HW;

    const unsigned ks_u = (unsigned)__cvta_generic_to_shared(smem);
    const unsigned vs_u = ks_u + 4 * KV_STAGE * 2;

    const int fr = t >> 2;              // fill row 0..63
    const int fc = (t & 3) * 2;         // fill chunk base

    const unsigned vrow = (lane >> 4) * 8 + (lane & 7);
    const unsigned vAoff = vrow * KV_ROWB + ((lane >> 3) & 1) * 16;
    const unsigned kAoff = lane * KV_ROWB;

    // Q A-fragments (already scaled in GEMM epilogue)
    unsigned Aq[4][4];
    #pragma unroll
    for (int kk = 0; kk < 4; kk++) {
        const int c0 = kk * 16 + 2 * gc;
        #pragma unroll
        for (int half8 = 0; half8 < 2; half8++) {
            const int c = c0 + half8 * 8;
            Aq[kk][half8 * 2 + 0] = h2u(__halves2half2(Qg[(size_t)(c    ) * HW + iw + gr],
                                                       Qg[(size_t)(c + 1) * HW + iw + gr]));
            Aq[kk][half8 * 2 + 1] = h2u(__halves2half2(Qg[(size_t)(c    ) * HW + iw + gr + 8],
                                                       Qg[(size_t)(c + 1) * HW + iw + gr + 8]));
        }
    }

    float Oacc[8][4];
    #pragma unroll
    for (int i = 0; i < 8; i++) {
        Oacc[i][0] = 0.f; Oacc[i][1] = 0.f; Oacc[i][2] = 0.f; Oacc[i][3] = 0.f;
    }
    float m0 = -CUDART_INF_F, m1 = -CUDART_INF_F;
    float l0 = 0.f, l1 = 0.f;

    // prefetch tiles 0,1 into stages 0,1
    #pragma unroll
    for (int pf = 0; pf < 2; pf++) {
        const unsigned s = pf * (KV_STAGE * 2);
        const int j0 = pf * 64;
        cpa16(ks_u + s + fr * KV_ROWB + (fc    ) * 16, Kg + (size_t)fr * HW + j0 + (fc    ) * 8);
        cpa16(ks_u + s + fr * KV_ROWB + (fc + 1) * 16, Kg + (size_t)fr * HW + j0 + (fc + 1) * 8);
        cpa16(vs_u + s + fr * KV_ROWB + (fc    ) * 16, Vg + (size_t)fr * HW + j0 + (fc    ) * 8);
        cpa16(vs_u + s + fr * KV_ROWB + (fc + 1) * 16, Vg + (size_t)fr * HW + j0 + (fc + 1) * 8);
        CP_COMMIT();
    }

    for (int jt = 0; jt < 64; jt++) {
        if (jt + 2 < 64) {
            const int j0 = (jt + 2) * 64;
            const unsigned s = ((jt + 2) & 3) * (KV_STAGE * 2);
            cpa16(ks_u + s + fr * KV_ROWB + (fc    ) * 16, Kg + (size_t)fr * HW + j0 + (fc    ) * 8);
            cpa16(ks_u + s + fr * KV_ROWB + (fc + 1) * 16, Kg + (size_t)fr * HW + j0 + (fc + 1) * 8);
            cpa16(vs_u + s + fr * KV_ROWB + (fc    ) * 16, Vg + (size_t)fr * HW + j0 + (fc    ) * 8);
            cpa16(vs_u + s + fr * KV_ROWB + (fc + 1) * 16, Vg + (size_t)fr * HW + j0 + (fc + 1) * 8);
        }
        CP_COMMIT();
        CP_WAIT(2);
        __syncthreads();

        const unsigned soff = (jt & 3) * (KV_STAGE * 2);
        const unsigned kA = ks_u + soff + kAoff;
        const unsigned vA = vs_u + soff + vAoff;

        // ---- S = Q K^T ----
        float S[8][4];
        #pragma unroll
        for (int nt = 0; nt < 8; nt++) {
            S[nt][0] = 0.f; S[nt][1] = 0.f; S[nt][2] = 0.f; S[nt][3] = 0.f;
        }
        #pragma unroll
        for (int nt = 0; nt < 8; nt++) {
            unsigned kb[4];
            ldmx4_t(kb, kA + nt * 16);
            mma_f16(S[nt], Aq[0], kb[0], kb[1]);
            mma_f16(S[nt], Aq[1], kb[2], kb[3]);
            ldmx4_t(kb, kA + 32 * KV_ROWB + nt * 16);
            mma_f16(S[nt], Aq[2], kb[0], kb[1]);
            mma_f16(S[nt], Aq[3], kb[2], kb[3]);
        }

        // ---- base-2 online softmax ----
        float mx0 = -CUDART_INF_F, mx1 = -CUDART_INF_F;
        #pragma unroll
        for (int nt = 0; nt < 8; nt++) {
            mx0 = fmaxf(mx0, fmaxf(S[nt][0], S[nt][1]));
            mx1 = fmaxf(mx1, fmaxf(S[nt][2], S[nt][3]));
        }
        mx0 = fmaxf(mx0, __shfl_xor_sync(0xffffffffu, mx0, 1));
        mx0 = fmaxf(mx0, __shfl_xor_sync(0xffffffffu, mx0, 2));
        mx1 = fmaxf(mx1, __shfl_xor_sync(0xffffffffu, mx1, 1));
        mx1 = fmaxf(mx1, __shfl_xor_sync(0xffffffffu, mx1, 2));

        const float mn0 = fmaxf(m0, mx0);
        const float mn1 = fmaxf(m1, mx1);
        const float al0 = ex2f(m0 - mn0);
        const float al1 = ex2f(m1 - mn1);
        float s0 = 0.f, s1 = 0.f;
        #pragma unroll
        for (int nt = 0; nt < 8; nt++) {
            float p0 = ex2f(S[nt][0] - mn0);
            float p1 = ex2f(S[nt][1] - mn0);
            float p2 = ex2f(S[nt][2] - mn1);
            float p3 = ex2f(S[nt][3] - mn1);
            S[nt][0] = p0; S[nt][1] = p1; S[nt][2] = p2; S[nt][3] = p3;
            s0 += p0 + p1; s1 += p2 + p3;
        }
        s0 += __shfl_xor_sync(0xffffffffu, s0, 1);
        s0 += __shfl_xor_sync(0xffffffffu, s0, 2);
        s1 += __shfl_xor_sync(0xffffffffu, s1, 1);
        s1 += __shfl_xor_sync(0xffffffffu, s1, 2);
        l0 = l0 * al0 + s0;  m0 = mn0;
        l1 = l1 * al1 + s1;  m1 = mn1;

        #pragma unroll
        for (int ct = 0; ct < 8; ct++) {
            Oacc[ct][0] *= al0; Oacc[ct][1] *= al0;
            Oacc[ct][2] *= al1; Oacc[ct][3] *= al1;
        }

        // ---- O += P V^T ----
        #pragma unroll
        for (int kk = 0; kk < 4; kk++) {
            unsigned pa[4];
            pa[0] = h2u(__floats2half2_rn(S[2*kk  ][0], S[2*kk  ][1]));
            pa[1] = h2u(__floats2half2_rn(S[2*kk  ][2], S[2*kk  ][3]));
            pa[2] = h2u(__floats2half2_rn(S[2*kk+1][0], S[2*kk+1][1]));
            pa[3] = h2u(__floats2half2_rn(S[2*kk+1][2], S[2*kk+1][3]));
            #pragma unroll
            for (int ct = 0; ct < 8; ct += 2) {
                unsigned vb[4];
                ldmx4(vb, vA + ct * (8 * KV_ROWB) + kk * 32);
                mma_f16(Oacc[ct    ], pa, vb[0], vb[1]);
                mma_f16(Oacc[ct + 1], pa, vb[2], vb[3]);
            }
        }
    }

    // ---- epilogue: normalize, write fp16 O directly ----
    const float inv0 = 1.f / l0;
    const float inv1 = 1.f / l1;
    __half* Og = g_oh + ((size_t)b * CCH + h * DH) * HW;
    #pragma unroll
    for (int ct = 0; ct < 8; ct++) {
        const int c = ct * 8 + 2 * gc;
        Og[(size_t)(c    ) * HW + iw + gr    ] = __float2half(Oacc[ct][0] * inv0);
        Og[(size_t)(c + 1) * HW + iw + gr    ] = __float2half(Oacc[ct][1] * inv0);
        Og[(size_t)(c    ) * HW + iw + gr + 8] = __float2half(Oacc[ct][2] * inv1);
        Og[(size_t)(c + 1) * HW + iw + gr + 8] = __float2half(Oacc[ct][3] * inv1);
    }
}

// ---------------------------------------------------------------------------
extern "C" void kernel_launch(void* const* d_in, const int* in_sizes, int n_in,
                              void* d_out, int out_size) {
    const float* x      = (const float*)d_in[0];
    const float* norm_w = (const float*)d_in[1];
    const float* norm_b = (const float*)d_in[2];
    const float* qkv_w  = (const float*)d_in[3];
    const float* qkv_b  = (const float*)d_in[4];
    const float* proj_w = (const float*)d_in[5];
    const float* proj_b = (const float*)d_in[6];
    float* out = (float*)d_out;

    cudaFuncSetAttribute(k_attn, cudaFuncAttributeMaxDynamicSharedMemorySize, ATTN_SMEM);

    k_stats<<<256, 256>>>(x);
    k_coef<<<4, 256>>>(norm_w, norm_b);
    k_wconv<<<1024, 256>>>(qkv_w, proj_w);
    k_xh<<<4096, 256>>>(x);
    k_gemm_h<0><<<dim3(32, 6, BB), 256>>>(qkv_b, nullptr, nullptr);
    k_attn<<<dim3(HW/128, BB*NH), 256, ATTN_SMEM>>>();
    k_gemm_h<1><<<dim3(32, 2, BB), 256>>>(proj_b, x, out);
}

// round 9
// speedup vs baseline: 8.5655x; 1.1474x over previous
#include <cuda_runtime.h>
#include <cuda_fp16.h>
#include <math_constants.h>
#include <cstddef>

// Problem constants
#define BB   4
#define CCH  256
#define NH   4
#define DH   64
#define GRP  8
#define HW   4096   // 64*64

// Scratch (device globals — no allocation allowed)
__device__ __half g_qkvh[(size_t)BB * 3 * CCH * HW];  // fp16 Q(scaled),K,V [b][768][4096]
__device__ __half g_xh  [(size_t)BB * CCH * HW];      // fp16 normalized x
__device__ __half g_oh  [(size_t)BB * CCH * HW];      // fp16 attention out
__device__ __half g_wqkvh[768 * 256];
__device__ __half g_wprojh[256 * 256];
__device__ float2 g_part[256];                        // partial (sum, sumsq)
__device__ float g_acoef[BB * CCH];
__device__ float g_bcoef[BB * CCH];

// ---------------------------------------------------------------------------
// helpers
// ---------------------------------------------------------------------------
__device__ __forceinline__ float ex2f(float x) {
    float y; asm("ex2.approx.f32 %0, %1;" : "=f"(y) : "f"(x)); return y;
}
__device__ __forceinline__ unsigned ex2h2(unsigned x) {
    unsigned y; asm("ex2.approx.f16x2 %0, %1;" : "=r"(y) : "r"(x)); return y;
}
__device__ __forceinline__ unsigned h2u(__half2 h) {
    return *reinterpret_cast<unsigned*>(&h);
}
__device__ __forceinline__ void mma_f16(float c[4], const unsigned a[4],
                                        unsigned b0, unsigned b1) {
    asm volatile(
        "mma.sync.aligned.m16n8k16.row.col.f32.f16.f16.f32 "
        "{%0,%1,%2,%3}, {%4,%5,%6,%7}, {%8,%9}, {%0,%1,%2,%3};"
        : "+f"(c[0]), "+f"(c[1]), "+f"(c[2]), "+f"(c[3])
        : "r"(a[0]), "r"(a[1]), "r"(a[2]), "r"(a[3]), "r"(b0), "r"(b1));
}
__device__ __forceinline__ void ldmx4_t(unsigned r[4], unsigned addr) {
    asm volatile("ldmatrix.sync.aligned.m8n8.x4.trans.shared.b16 {%0,%1,%2,%3}, [%4];"
        : "=r"(r[0]), "=r"(r[1]), "=r"(r[2]), "=r"(r[3]) : "r"(addr));
}
__device__ __forceinline__ void ldmx4(unsigned r[4], unsigned addr) {
    asm volatile("ldmatrix.sync.aligned.m8n8.x4.shared.b16 {%0,%1,%2,%3}, [%4];"
        : "=r"(r[0]), "=r"(r[1]), "=r"(r[2]), "=r"(r[3]) : "r"(addr));
}
__device__ __forceinline__ void ldmx2(unsigned r[2], unsigned addr) {
    asm volatile("ldmatrix.sync.aligned.m8n8.x2.shared.b16 {%0,%1}, [%2];"
        : "=r"(r[0]), "=r"(r[1]) : "r"(addr));
}
__device__ __forceinline__ void cpa16(unsigned dst, const void* src) {
    asm volatile("cp.async.cg.shared.global [%0], [%1], 16;" :: "r"(dst), "l"(src));
}
#define CP_COMMIT()  asm volatile("cp.async.commit_group;")
#define CP_WAIT(N)   asm volatile("cp.async.wait_group " #N ";")

// ---------------------------------------------------------------------------
// Kernel 1: partial sums, 256 blocks
// ---------------------------------------------------------------------------
__global__ void k_stats(const float* __restrict__ x) {
    const int bid = blockIdx.x;
    const float4* p = reinterpret_cast<const float4*>(x + (size_t)bid * 16384);
    float s = 0.f, s2 = 0.f;
    for (int i = threadIdx.x; i < 4096; i += 256) {
        float4 v = p[i];
        s  += v.x + v.y + v.z + v.w;
        s2 += v.x*v.x + v.y*v.y + v.z*v.z + v.w*v.w;
    }
    __shared__ float rs[256], rs2[256];
    rs[threadIdx.x] = s; rs2[threadIdx.x] = s2;
    __syncthreads();
    for (int off = 128; off > 0; off >>= 1) {
        if (threadIdx.x < off) {
            rs[threadIdx.x]  += rs[threadIdx.x + off];
            rs2[threadIdx.x] += rs2[threadIdx.x + off];
        }
        __syncthreads();
    }
    if (threadIdx.x == 0) g_part[bid] = make_float2(rs[0], rs2[0]);
}

// ---------------------------------------------------------------------------
// Kernel 2: finalize stats + per-(b,c) affine coefficients
// ---------------------------------------------------------------------------
__global__ void k_coef(const float* __restrict__ nw, const float* __restrict__ nb) {
    int t = blockIdx.x * 256 + threadIdx.x;
    if (t >= BB * CCH) return;
    int b = t >> 8, c = t & 255;
    int gidx = b * GRP + (c >> 5);
    float s = 0.f, s2 = 0.f;
    #pragma unroll
    for (int i = 0; i < 8; i++) {
        float2 p = g_part[gidx * 8 + i];
        s += p.x; s2 += p.y;
    }
    float mean = s * (1.f / 131072.f);
    float var  = s2 * (1.f / 131072.f) - mean * mean;
    float rstd = rsqrtf(var + 1e-5f);
    float a = nw[c] * rstd;
    g_acoef[t] = a;
    g_bcoef[t] = nb[c] - mean * a;
}

// ---------------------------------------------------------------------------
// Kernel 2b: convert weights to fp16
// ---------------------------------------------------------------------------
__global__ void k_wconv(const float* __restrict__ qkv_w,
                        const float* __restrict__ proj_w) {
    int i = blockIdx.x * 256 + threadIdx.x;
    if (i < 768 * 256) g_wqkvh[i] = __float2half(qkv_w[i]);
    else               g_wprojh[i - 768 * 256] = __float2half(proj_w[i - 768 * 256]);
}

// ---------------------------------------------------------------------------
// Kernel 2c: g_xh = fp16( x * a + bc ), float4 path
// ---------------------------------------------------------------------------
__global__ void k_xh(const float* __restrict__ x) {
    int id = blockIdx.x * 256 + threadIdx.x;
    int bc = id >> 10;
    float a = g_acoef[bc], bb = g_bcoef[bc];
    float4 v = reinterpret_cast<const float4*>(x)[id];
    __half2 lo = __floats2half2_rn(fmaf(v.x, a, bb), fmaf(v.y, a, bb));
    __half2 hi = __floats2half2_rn(fmaf(v.z, a, bb), fmaf(v.w, a, bb));
    reinterpret_cast<uint2*>(g_xh)[id] = make_uint2(h2u(lo), h2u(hi));
}

// ---------------------------------------------------------------------------
// Kernel 3/5: fp16 tensor-core GEMM, 128x128 CTA tile, 32x64 warp tile.
// ---------------------------------------------------------------------------
#define AS_STAGE  (128 * 40)
#define BS_STAGE  (32 * 136)
#define QSCALE 0.180336880111f  // 0.125 * log2(e)

template<int MODE>
__global__ void __launch_bounds__(256, 2)
k_gemm_h(const float* __restrict__ bias,
         const float* __restrict__ resid,
         float* __restrict__ outp)
{
    __shared__ __half As[2 * AS_STAGE];
    __shared__ __half Bs[2 * BS_STAGE];

    const int t = threadIdx.x;
    const int w = t >> 5, lane = t & 31;
    const int gr = lane >> 2, gc = lane & 3;
    const int n0 = blockIdx.x * 128;
    const int m0 = blockIdx.y * 128;
    const int b  = blockIdx.z;
    const int mw = (w & 3) * 32;
    const int nw = (w >> 2) * 64;

    const __half* Wh = (MODE == 0) ? g_wqkvh : g_wprojh;
    const __half* Xh = (MODE == 0) ? g_xh    : g_oh;

    const unsigned as_u = (unsigned)__cvta_generic_to_shared(As);
    const unsigned bs_u = (unsigned)__cvta_generic_to_shared(Bs);

    const int ar = t >> 1;
    const int ac = (t & 1) * 2;
    const int br = t >> 3;
    const int bcw = (t & 7) * 2;

    float acc[2][8][4];
    #pragma unroll
    for (int mt = 0; mt < 2; mt++)
        #pragma unroll
        for (int nt = 0; nt < 8; nt++) {
            acc[mt][nt][0] = 0.f; acc[mt][nt][1] = 0.f;
            acc[mt][nt][2] = 0.f; acc[mt][nt][3] = 0.f;
        }

    {
        cpa16(as_u + ar * 80 + (ac    ) * 16, Wh + (size_t)(m0 + ar) * 256 + (ac    ) * 8);
        cpa16(as_u + ar * 80 + (ac + 1) * 16, Wh + (size_t)(m0 + ar) * 256 + (ac + 1) * 8);
        cpa16(bs_u + br * 272 + (bcw    ) * 16, Xh + ((size_t)b * CCH + br) * HW + n0 + (bcw    ) * 8);
        cpa16(bs_u + br * 272 + (bcw + 1) * 16, Xh + ((size_t)b * CCH + br) * HW + n0 + (bcw + 1) * 8);
        CP_COMMIT();
    }

    #pragma unroll
    for (int c = 0; c < 8; c++) {
        if (c < 7) {
            const int kk = (c + 1) * 32;
            const unsigned sa = ((c + 1) & 1) * (AS_STAGE * 2);
            const unsigned sb = ((c + 1) & 1) * (BS_STAGE * 2);
            cpa16(as_u + sa + ar * 80 + (ac    ) * 16, Wh + (size_t)(m0 + ar) * 256 + kk + (ac    ) * 8);
            cpa16(as_u + sa + ar * 80 + (ac + 1) * 16, Wh + (size_t)(m0 + ar) * 256 + kk + (ac + 1) * 8);
            cpa16(bs_u + sb + br * 272 + (bcw    ) * 16, Xh + ((size_t)b * CCH + kk + br) * HW + n0 + (bcw    ) * 8);
            cpa16(bs_u + sb + br * 272 + (bcw + 1) * 16, Xh + ((size_t)b * CCH + kk + br) * HW + n0 + (bcw + 1) * 8);
            CP_COMMIT();
            CP_WAIT(1);
        } else {
            CP_WAIT(0);
        }
        __syncthreads();

        const unsigned abase = as_u + (c & 1) * (AS_STAGE * 2);
        const unsigned bbase = bs_u + (c & 1) * (BS_STAGE * 2);

        unsigned a[2][2][4];
        #pragma unroll
        for (int mt = 0; mt < 2; mt++)
            #pragma unroll
            for (int kq = 0; kq < 2; kq++)
                ldmx4(a[mt][kq], abase + (mw + mt * 16 + (lane & 15)) * 80
                                  + kq * 32 + (lane >> 4) * 16);

        #pragma unroll
        for (int nt = 0; nt < 8; nt++) {
            unsigned bb[4];
            ldmx4_t(bb, bbase + lane * 272 + (nw + nt * 8) * 2);
            #pragma unroll
            for (int mt = 0; mt < 2; mt++) {
                mma_f16(acc[mt][nt], a[mt][0], bb[0], bb[1]);
                mma_f16(acc[mt][nt], a[mt][1], bb[2], bb[3]);
            }
        }
        __syncthreads();
    }

    // ---- epilogue ----
    const float osc = (MODE == 0 && m0 < 256) ? QSCALE : 1.f;
    #pragma unroll
    for (int mt = 0; mt < 2; mt++) {
        const int mA = m0 + mw + mt * 16 + gr;
        const int mB = mA + 8;
        const float bA = bias[mA], bBv = bias[mB];
        #pragma unroll
        for (int nt = 0; nt < 8; nt++) {
            const int n = n0 + nw + nt * 8 + 2 * gc;
            float v0 = (acc[mt][nt][0] + bA) * osc, v1 = (acc[mt][nt][1] + bA) * osc;
            float v2 = (acc[mt][nt][2] + bBv) * osc, v3 = (acc[mt][nt][3] + bBv) * osc;
            if (MODE == 0) {
                *reinterpret_cast<__half2*>(&g_qkvh[((size_t)b * 768 + mA) * HW + n]) = __floats2half2_rn(v0, v1);
                *reinterpret_cast<__half2*>(&g_qkvh[((size_t)b * 768 + mB) * HW + n]) = __floats2half2_rn(v2, v3);
            } else {
                const size_t oA = ((size_t)b * CCH + mA) * HW + n;
                const size_t oB = ((size_t)b * CCH + mB) * HW + n;
                float2 xA = *reinterpret_cast<const float2*>(&resid[oA]);
                float2 xB = *reinterpret_cast<const float2*>(&resid[oB]);
                *reinterpret_cast<float2*>(&outp[oA]) = make_float2(v0 + xA.x, v1 + xA.y);
                *reinterpret_cast<float2*>(&outp[oB]) = make_float2(v2 + xB.x, v3 + xB.y);
            }
        }
    }
}

// ---------------------------------------------------------------------------
// Kernel 4: flash attention, fp16 mma + ldmatrix + 4-stage cp.async pipeline.
// Softmax: P = ex2.approx.f16x2 (packed-half exp); row sums l via a ones-
// channel MMA (V smem extended to 72 rows/stage; row 64 = ones).
// ---------------------------------------------------------------------------
#define KV_ROWB   144                 // bytes per smem row (72 halves)
#define KSTAGE_B  (64 * KV_ROWB)      // 9216 B
#define VSTAGE_B  (72 * KV_ROWB)      // 10368 B (64 data + 8 ones/zero rows)
#define ATTN_SMEM (4 * (KSTAGE_B + VSTAGE_B))   // 78336 B

__global__ void __launch_bounds__(256, 2) k_attn() {
    extern __shared__ __half smem[];

    const int t    = threadIdx.x;
    const int w    = t >> 5;
    const int lane = t & 31;
    const int gr   = lane >> 2;
    const int gc   = lane & 3;

    const int bh = blockIdx.y;
    const int b  = bh >> 2, h = bh & 3;
    const int i0 = blockIdx.x * 128;
    const int iw = i0 + w * 16;

    const __half* Qg = g_qkvh + ((size_t)b * 768 +       h * DH) * HW;
    const __half* Kg = g_qkvh + ((size_t)b * 768 + 256 + h * DH) * HW;
    const __half* Vg = g_qkvh + ((size_t)b * 768 + 512 + h * DH) * HW;

    const unsigned ks_u = (unsigned)__cvta_generic_to_shared(smem);
    const unsigned vb_u = ks_u + 4 * KSTAGE_B;

    const int fr = t >> 2;              // fill row 0..63
    const int fc = (t & 3) * 2;         // fill chunk base

    const unsigned vrow = (lane >> 4) * 8 + (lane & 7);
    const unsigned vAoff = vrow * KV_ROWB + ((lane >> 3) & 1) * 16;
    const unsigned vSoff = (64 + (lane & 7)) * KV_ROWB + ((lane >> 3) & 1) * 16;
    const unsigned kAoff = lane * KV_ROWB;

    // init ones/zero rows (64..71) of all 4 V stages
    {
        __half* Vb = smem + 4 * 64 * 72;   // halves
        const __half one = __float2half(1.f);
        const __half zer = __float2half(0.f);
        for (int i = t; i < 4 * 8 * 72; i += 256) {
            int s  = i / (8 * 72);
            int rm = i % (8 * 72);
            int r  = rm / 72, cc = rm % 72;
            Vb[s * (72 * 72) + (64 + r) * 72 + cc] = (r == 0) ? one : zer;
        }
    }

    // Q A-fragments (already scaled in GEMM epilogue)
    unsigned Aq[4][4];
    #pragma unroll
    for (int kk = 0; kk < 4; kk++) {
        const int c0 = kk * 16 + 2 * gc;
        #pragma unroll
        for (int half8 = 0; half8 < 2; half8++) {
            const int c = c0 + half8 * 8;
            Aq[kk][half8 * 2 + 0] = h2u(__halves2half2(Qg[(size_t)(c    ) * HW + iw + gr],
                                                       Qg[(size_t)(c + 1) * HW + iw + gr]));
            Aq[kk][half8 * 2 + 1] = h2u(__halves2half2(Qg[(size_t)(c    ) * HW + iw + gr + 8],
                                                       Qg[(size_t)(c + 1) * HW + iw + gr + 8]));
        }
    }

    float Oacc[8][4];
    #pragma unroll
    for (int i = 0; i < 8; i++) {
        Oacc[i][0] = 0.f; Oacc[i][1] = 0.f; Oacc[i][2] = 0.f; Oacc[i][3] = 0.f;
    }
    float Osum[4] = {0.f, 0.f, 0.f, 0.f};
    float m0 = -CUDART_INF_F, m1 = -CUDART_INF_F;

    // prefetch tiles 0,1
    #pragma unroll
    for (int pf = 0; pf < 2; pf++) {
        const int j0 = pf * 64;
        const unsigned sk = ks_u + pf * KSTAGE_B;
        const unsigned sv = vb_u + pf * VSTAGE_B;
        cpa16(sk + fr * KV_ROWB + (fc    ) * 16, Kg + (size_t)fr * HW + j0 + (fc    ) * 8);
        cpa16(sk + fr * KV_ROWB + (fc + 1) * 16, Kg + (size_t)fr * HW + j0 + (fc + 1) * 8);
        cpa16(sv + fr * KV_ROWB + (fc    ) * 16, Vg + (size_t)fr * HW + j0 + (fc    ) * 8);
        cpa16(sv + fr * KV_ROWB + (fc + 1) * 16, Vg + (size_t)fr * HW + j0 + (fc + 1) * 8);
        CP_COMMIT();
    }

    for (int jt = 0; jt < 64; jt++) {
        if (jt + 2 < 64) {
            const int j0 = (jt + 2) * 64;
            const unsigned sk = ks_u + ((jt + 2) & 3) * KSTAGE_B;
            const unsigned sv = vb_u + ((jt + 2) & 3) * VSTAGE_B;
            cpa16(sk + fr * KV_ROWB + (fc    ) * 16, Kg + (size_t)fr * HW + j0 + (fc    ) * 8);
            cpa16(sk + fr * KV_ROWB + (fc + 1) * 16, Kg + (size_t)fr * HW + j0 + (fc + 1) * 8);
            cpa16(sv + fr * KV_ROWB + (fc    ) * 16, Vg + (size_t)fr * HW + j0 + (fc    ) * 8);
            cpa16(sv + fr * KV_ROWB + (fc + 1) * 16, Vg + (size_t)fr * HW + j0 + (fc + 1) * 8);
        }
        CP_COMMIT();
        CP_WAIT(2);
        __syncthreads();

        const unsigned kA = ks_u + (jt & 3) * KSTAGE_B + kAoff;
        const unsigned vA = vb_u + (jt & 3) * VSTAGE_B + vAoff;
        const unsigned vS = vb_u + (jt & 3) * VSTAGE_B + vSoff;

        // ---- S = Q K^T ----
        float S[8][4];
        #pragma unroll
        for (int nt = 0; nt < 8; nt++) {
            S[nt][0] = 0.f; S[nt][1] = 0.f; S[nt][2] = 0.f; S[nt][3] = 0.f;
        }
        #pragma unroll
        for (int nt = 0; nt < 8; nt++) {
            unsigned kb[4];
            ldmx4_t(kb, kA + nt * 16);
            mma_f16(S[nt], Aq[0], kb[0], kb[1]);
            mma_f16(S[nt], Aq[1], kb[2], kb[3]);
            ldmx4_t(kb, kA + 32 * KV_ROWB + nt * 16);
            mma_f16(S[nt], Aq[2], kb[0], kb[1]);
            mma_f16(S[nt], Aq[3], kb[2], kb[3]);
        }

        // ---- max update (fp32) ----
        float mx0 = -CUDART_INF_F, mx1 = -CUDART_INF_F;
        #pragma unroll
        for (int nt = 0; nt < 8; nt++) {
            mx0 = fmaxf(mx0, fmaxf(S[nt][0], S[nt][1]));
            mx1 = fmaxf(mx1, fmaxf(S[nt][2], S[nt][3]));
        }
        mx0 = fmaxf(mx0, __shfl_xor_sync(0xffffffffu, mx0, 1));
        mx0 = fmaxf(mx0, __shfl_xor_sync(0xffffffffu, mx0, 2));
        mx1 = fmaxf(mx1, __shfl_xor_sync(0xffffffffu, mx1, 1));
        mx1 = fmaxf(mx1, __shfl_xor_sync(0xffffffffu, mx1, 2));

        const float mn0 = fmaxf(m0, mx0);
        const float mn1 = fmaxf(m1, mx1);
        const float al0 = ex2f(m0 - mn0);
        const float al1 = ex2f(m1 - mn1);
        m0 = mn0; m1 = mn1;

        // ---- P = ex2(S - mn) in packed half ----
        unsigned Ph0[8], Ph1[8];
        #pragma unroll
        for (int nt = 0; nt < 8; nt++) {
            Ph0[nt] = ex2h2(h2u(__floats2half2_rn(S[nt][0] - mn0, S[nt][1] - mn0)));
            Ph1[nt] = ex2h2(h2u(__floats2half2_rn(S[nt][2] - mn1, S[nt][3] - mn1)));
        }

        // ---- rescale accumulators (incl. sum channel) ----
        #pragma unroll
        for (int ct = 0; ct < 8; ct++) {
            Oacc[ct][0] *= al0; Oacc[ct][1] *= al0;
            Oacc[ct][2] *= al1; Oacc[ct][3] *= al1;
        }
        Osum[0] *= al0; Osum[1] *= al0;
        Osum[2] *= al1; Osum[3] *= al1;

        // ---- O += P V^T ; l via ones-channel ----
        #pragma unroll
        for (int kk = 0; kk < 4; kk++) {
            unsigned pa[4];
            pa[0] = Ph0[2*kk];   pa[1] = Ph1[2*kk];
            pa[2] = Ph0[2*kk+1]; pa[3] = Ph1[2*kk+1];
            #pragma unroll
            for (int ct = 0; ct < 8; ct += 2) {
                unsigned vb[4];
                ldmx4(vb, vA + ct * (8 * KV_ROWB) + kk * 32);
                mma_f16(Oacc[ct    ], pa, vb[0], vb[1]);
                mma_f16(Oacc[ct + 1], pa, vb[2], vb[3]);
            }
            unsigned sbv[2];
            ldmx2(sbv, vS + kk * 32);
            mma_f16(Osum, pa, sbv[0], sbv[1]);
        }
    }

    // ---- epilogue: l from sum channel (gc==0 lanes), normalize, write ----
    const float lA = __shfl_sync(0xffffffffu, Osum[0], lane & 28);
    const float lB = __shfl_sync(0xffffffffu, Osum[2], lane & 28);
    const float inv0 = 1.f / lA;
    const float inv1 = 1.f / lB;
    __half* Og = g_oh + ((size_t)b * CCH + h * DH) * HW;
    #pragma unroll
    for (int ct = 0; ct < 8; ct++) {
        const int c = ct * 8 + 2 * gc;
        Og[(size_t)(c    ) * HW + iw + gr    ] = __float2half(Oacc[ct][0] * inv0);
        Og[(size_t)(c + 1) * HW + iw + gr    ] = __float2half(Oacc[ct][1] * inv0);
        Og[(size_t)(c    ) * HW + iw + gr + 8] = __float2half(Oacc[ct][2] * inv1);
        Og[(size_t)(c + 1) * HW + iw + gr + 8] = __float2half(Oacc[ct][3] * inv1);
    }
}

// ---------------------------------------------------------------------------
extern "C" void kernel_launch(void* const* d_in, const int* in_sizes, int n_in,
                              void* d_out, int out_size) {
    const float* x      = (const float*)d_in[0];
    const float* norm_w = (const float*)d_in[1];
    const float* norm_b = (const float*)d_in[2];
    const float* qkv_w  = (const float*)d_in[3];
    const float* qkv_b  = (const float*)d_in[4];
    const float* proj_w = (const float*)d_in[5];
    const float* proj_b = (const float*)d_in[6];
    float* out = (float*)d_out;

    cudaFuncSetAttribute(k_attn, cudaFuncAttributeMaxDynamicSharedMemorySize, ATTN_SMEM);

    k_stats<<<256, 256>>>(x);
    k_coef<<<4, 256>>>(norm_w, norm_b);
    k_wconv<<<1024, 256>>>(qkv_w, proj_w);
    k_xh<<<4096, 256>>>(x);
    k_gemm_h<0><<<dim3(32, 6, BB), 256>>>(qkv_b, nullptr, nullptr);
    k_attn<<<dim3(HW/128, BB*NH), 256, ATTN_SMEM>>>();
    k_gemm_h<1><<<dim3(32, 2, BB), 256>>>(proj_b, x, out);
}

// round 11
// speedup vs baseline: 8.8063x; 1.0281x over previous
#include <cuda_runtime.h>
#include <cuda_fp16.h>
#include <math_constants.h>
#include <cstddef>

// Problem constants
#define BB   4
#define CCH  256
#define NH   4
#define DH   64
#define GRP  8
#define HW   4096   // 64*64

// Scratch (device globals — no allocation allowed)
__device__ __half g_qkvh[(size_t)BB * 3 * CCH * HW];  // fp16 Q(scaled),K,V [b][768][4096]
__device__ __half g_xh  [(size_t)BB * CCH * HW];      // fp16 normalized x
__device__ __half g_oh  [(size_t)BB * CCH * HW];      // fp16 attention out
__device__ __half g_wqkvh[768 * 256];
__device__ __half g_wprojh[256 * 256];
__device__ float2 g_part[256];                        // partial (sum, sumsq)
__device__ float g_acoef[BB * CCH];
__device__ float g_bcoef[BB * CCH];

// ---------------------------------------------------------------------------
// helpers
// ---------------------------------------------------------------------------
__device__ __forceinline__ float ex2f(float x) {
    float y; asm("ex2.approx.f32 %0, %1;" : "=f"(y) : "f"(x)); return y;
}
__device__ __forceinline__ unsigned ex2h2(unsigned x) {
    unsigned y; asm("ex2.approx.f16x2 %0, %1;" : "=r"(y) : "r"(x)); return y;
}
__device__ __forceinline__ unsigned h2u(__half2 h) {
    return *reinterpret_cast<unsigned*>(&h);
}
__device__ __forceinline__ void mma_f16(float c[4], const unsigned a[4],
                                        unsigned b0, unsigned b1) {
    asm volatile(
        "mma.sync.aligned.m16n8k16.row.col.f32.f16.f16.f32 "
        "{%0,%1,%2,%3}, {%4,%5,%6,%7}, {%8,%9}, {%0,%1,%2,%3};"
        : "+f"(c[0]), "+f"(c[1]), "+f"(c[2]), "+f"(c[3])
        : "r"(a[0]), "r"(a[1]), "r"(a[2]), "r"(a[3]), "r"(b0), "r"(b1));
}
__device__ __forceinline__ void ldmx4_t(unsigned r[4], unsigned addr) {
    asm volatile("ldmatrix.sync.aligned.m8n8.x4.trans.shared.b16 {%0,%1,%2,%3}, [%4];"
        : "=r"(r[0]), "=r"(r[1]), "=r"(r[2]), "=r"(r[3]) : "r"(addr));
}
__device__ __forceinline__ void ldmx4(unsigned r[4], unsigned addr) {
    asm volatile("ldmatrix.sync.aligned.m8n8.x4.shared.b16 {%0,%1,%2,%3}, [%4];"
        : "=r"(r[0]), "=r"(r[1]), "=r"(r[2]), "=r"(r[3]) : "r"(addr));
}
__device__ __forceinline__ void ldmx2(unsigned r[2], unsigned addr) {
    asm volatile("ldmatrix.sync.aligned.m8n8.x2.shared.b16 {%0,%1}, [%2];"
        : "=r"(r[0]), "=r"(r[1]) : "r"(addr));
}
__device__ __forceinline__ void cpa16(unsigned dst, const void* src) {
    asm volatile("cp.async.cg.shared.global [%0], [%1], 16;" :: "r"(dst), "l"(src));
}
#define CP_COMMIT()  asm volatile("cp.async.commit_group;")
#define CP_WAIT(N)   asm volatile("cp.async.wait_group " #N ";")

// ---------------------------------------------------------------------------
// Kernel 1: partial sums, 256 blocks
// ---------------------------------------------------------------------------
__global__ void k_stats(const float* __restrict__ x) {
    const int bid = blockIdx.x;
    const float4* p = reinterpret_cast<const float4*>(x + (size_t)bid * 16384);
    float s = 0.f, s2 = 0.f;
    for (int i = threadIdx.x; i < 4096; i += 256) {
        float4 v = p[i];
        s  += v.x + v.y + v.z + v.w;
        s2 += v.x*v.x + v.y*v.y + v.z*v.z + v.w*v.w;
    }
    __shared__ float rs[256], rs2[256];
    rs[threadIdx.x] = s; rs2[threadIdx.x] = s2;
    __syncthreads();
    for (int off = 128; off > 0; off >>= 1) {
        if (threadIdx.x < off) {
            rs[threadIdx.x]  += rs[threadIdx.x + off];
            rs2[threadIdx.x] += rs2[threadIdx.x + off];
        }
        __syncthreads();
    }
    if (threadIdx.x == 0) g_part[bid] = make_float2(rs[0], rs2[0]);
}

// ---------------------------------------------------------------------------
// Kernel 2: finalize stats + per-(b,c) affine coefficients
// ---------------------------------------------------------------------------
__global__ void k_coef(const float* __restrict__ nw, const float* __restrict__ nb) {
    int t = blockIdx.x * 256 + threadIdx.x;
    if (t >= BB * CCH) return;
    int b = t >> 8, c = t & 255;
    int gidx = b * GRP + (c >> 5);
    float s = 0.f, s2 = 0.f;
    #pragma unroll
    for (int i = 0; i < 8; i++) {
        float2 p = g_part[gidx * 8 + i];
        s += p.x; s2 += p.y;
    }
    float mean = s * (1.f / 131072.f);
    float var  = s2 * (1.f / 131072.f) - mean * mean;
    float rstd = rsqrtf(var + 1e-5f);
    float a = nw[c] * rstd;
    g_acoef[t] = a;
    g_bcoef[t] = nb[c] - mean * a;
}

// ---------------------------------------------------------------------------
// Kernel 2c: fused — blocks [0,2048): g_xh = fp16(x*a+bc), 2 float4/thread;
//            blocks [2048,2304): weight conversion to fp16 (float4 path).
// ---------------------------------------------------------------------------
__global__ void k_xh(const float* __restrict__ x,
                     const float* __restrict__ qkv_w,
                     const float* __restrict__ proj_w) {
    if (blockIdx.x < 2048) {
        #pragma unroll
        for (int half_part = 0; half_part < 2; half_part++) {
            int id = half_part * (2048 * 256) + blockIdx.x * 256 + threadIdx.x;
            int bc = id >> 10;
            float a = g_acoef[bc], bb = g_bcoef[bc];
            float4 v = reinterpret_cast<const float4*>(x)[id];
            __half2 lo = __floats2half2_rn(fmaf(v.x, a, bb), fmaf(v.y, a, bb));
            __half2 hi = __floats2half2_rn(fmaf(v.z, a, bb), fmaf(v.w, a, bb));
            reinterpret_cast<uint2*>(g_xh)[id] = make_uint2(h2u(lo), h2u(hi));
        }
    } else {
        int i4 = (blockIdx.x - 2048) * 256 + threadIdx.x;   // float4 index, 0..65535
        int i  = i4 * 4;
        float4 v;
        __half* dst;
        if (i < 768 * 256) {
            v = reinterpret_cast<const float4*>(qkv_w)[i4];
            dst = g_wqkvh + i;
        } else {
            v = reinterpret_cast<const float4*>(proj_w)[i4 - 49152];
            dst = g_wprojh + (i - 768 * 256);
        }
        __half2 lo = __floats2half2_rn(v.x, v.y);
        __half2 hi = __floats2half2_rn(v.z, v.w);
        *reinterpret_cast<uint2*>(dst) = make_uint2(h2u(lo), h2u(hi));
    }
}

// ---------------------------------------------------------------------------
// Kernel 3/5: fp16 tensor-core GEMM, 128x128 CTA tile, 32x64 warp tile.
// 4-stage cp.async pipeline, prefetch distance 2, one sync per chunk.
// ---------------------------------------------------------------------------
#define AS_STAGE  (128 * 40)     // halves per A stage
#define BS_STAGE  (32 * 136)     // halves per B stage
#define GEMM_SMEM (4 * (AS_STAGE + BS_STAGE) * 2)   // 75776 B
#define QSCALE 0.180336880111f   // 0.125 * log2(e)

template<int MODE>
__global__ void __launch_bounds__(256, 2)
k_gemm_h(const float* __restrict__ bias,
         const float* __restrict__ resid,
         float* __restrict__ outp)
{
    extern __shared__ __half gsm[];

    const int t = threadIdx.x;
    const int w = t >> 5, lane = t & 31;
    const int gr = lane >> 2, gc = lane & 3;
    const int n0 = blockIdx.x * 128;
    const int m0 = blockIdx.y * 128;
    const int b  = blockIdx.z;
    const int mw = (w & 3) * 32;
    const int nw = (w >> 2) * 64;

    const __half* Wh = (MODE == 0) ? g_wqkvh : g_wprojh;
    const __half* Xh = (MODE == 0) ? g_xh    : g_oh;

    const unsigned as_u = (unsigned)__cvta_generic_to_shared(gsm);
    const unsigned bs_u = as_u + 4 * AS_STAGE * 2;

    const int ar = t >> 1;
    const int ac = (t & 1) * 2;
    const int br = t >> 3;
    const int bcw = (t & 7) * 2;

    float acc[2][8][4];
    #pragma unroll
    for (int mt = 0; mt < 2; mt++)
        #pragma unroll
        for (int nt = 0; nt < 8; nt++) {
            acc[mt][nt][0] = 0.f; acc[mt][nt][1] = 0.f;
            acc[mt][nt][2] = 0.f; acc[mt][nt][3] = 0.f;
        }

    // prefetch chunks 0,1
    #pragma unroll
    for (int p = 0; p < 2; p++) {
        const int kk = p * 32;
        const unsigned sa = as_u + p * (AS_STAGE * 2);
        const unsigned sb = bs_u + p * (BS_STAGE * 2);
        cpa16(sa + ar * 80 + (ac    ) * 16, Wh + (size_t)(m0 + ar) * 256 + kk + (ac    ) * 8);
        cpa16(sa + ar * 80 + (ac + 1) * 16, Wh + (size_t)(m0 + ar) * 256 + kk + (ac + 1) * 8);
        cpa16(sb + br * 272 + (bcw    ) * 16, Xh + ((size_t)b * CCH + kk + br) * HW + n0 + (bcw    ) * 8);
        cpa16(sb + br * 272 + (bcw + 1) * 16, Xh + ((size_t)b * CCH + kk + br) * HW + n0 + (bcw + 1) * 8);
        CP_COMMIT();
    }

    #pragma unroll
    for (int c = 0; c < 8; c++) {
        if (c + 2 < 8) {
            const int kk = (c + 2) * 32;
            const unsigned sa = as_u + ((c + 2) & 3) * (AS_STAGE * 2);
            const unsigned sb = bs_u + ((c + 2) & 3) * (BS_STAGE * 2);
            cpa16(sa + ar * 80 + (ac    ) * 16, Wh + (size_t)(m0 + ar) * 256 + kk + (ac    ) * 8);
            cpa16(sa + ar * 80 + (ac + 1) * 16, Wh + (size_t)(m0 + ar) * 256 + kk + (ac + 1) * 8);
            cpa16(sb + br * 272 + (bcw    ) * 16, Xh + ((size_t)b * CCH + kk + br) * HW + n0 + (bcw    ) * 8);
            cpa16(sb + br * 272 + (bcw + 1) * 16, Xh + ((size_t)b * CCH + kk + br) * HW + n0 + (bcw + 1) * 8);
        }
        CP_COMMIT();
        CP_WAIT(2);
        __syncthreads();

        const unsigned abase = as_u + (c & 3) * (AS_STAGE * 2);
        const unsigned bbase = bs_u + (c & 3) * (BS_STAGE * 2);

        unsigned a[2][2][4];
        #pragma unroll
        for (int mt = 0; mt < 2; mt++)
            #pragma unroll
            for (int kq = 0; kq < 2; kq++)
                ldmx4(a[mt][kq], abase + (mw + mt * 16 + (lane & 15)) * 80
                                  + kq * 32 + (lane >> 4) * 16);

        #pragma unroll
        for (int nt = 0; nt < 8; nt++) {
            unsigned bb[4];
            ldmx4_t(bb, bbase + lane * 272 + (nw + nt * 8) * 2);
            #pragma unroll
            for (int mt = 0; mt < 2; mt++) {
                mma_f16(acc[mt][nt], a[mt][0], bb[0], bb[1]);
                mma_f16(acc[mt][nt], a[mt][1], bb[2], bb[3]);
            }
        }
    }

    // ---- epilogue ----
    const float osc = (MODE == 0 && m0 < 256) ? QSCALE : 1.f;
    #pragma unroll
    for (int mt = 0; mt < 2; mt++) {
        const int mA = m0 + mw + mt * 16 + gr;
        const int mB = mA + 8;
        const float bA = bias[mA], bBv = bias[mB];
        #pragma unroll
        for (int nt = 0; nt < 8; nt++) {
            const int n = n0 + nw + nt * 8 + 2 * gc;
            float v0 = (acc[mt][nt][0] + bA) * osc, v1 = (acc[mt][nt][1] + bA) * osc;
            float v2 = (acc[mt][nt][2] + bBv) * osc, v3 = (acc[mt][nt][3] + bBv) * osc;
            if (MODE == 0) {
                *reinterpret_cast<__half2*>(&g_qkvh[((size_t)b * 768 + mA) * HW + n]) = __floats2half2_rn(v0, v1);
                *reinterpret_cast<__half2*>(&g_qkvh[((size_t)b * 768 + mB) * HW + n]) = __floats2half2_rn(v2, v3);
            } else {
                const size_t oA = ((size_t)b * CCH + mA) * HW + n;
                const size_t oB = ((size_t)b * CCH + mB) * HW + n;
                float2 xA = *reinterpret_cast<const float2*>(&resid[oA]);
                float2 xB = *reinterpret_cast<const float2*>(&resid[oB]);
                *reinterpret_cast<float2*>(&outp[oA]) = make_float2(v0 + xA.x, v1 + xA.y);
                *reinterpret_cast<float2*>(&outp[oB]) = make_float2(v2 + xB.x, v3 + xB.y);
            }
        }
    }
}

// ---------------------------------------------------------------------------
// Kernel 4: flash attention, fp16 mma + ldmatrix + 4-stage cp.async pipeline.
// Softmax: P via ex2.approx.f16x2; row sums via ones-channel MMA;
// accumulator rescale skipped (warp-uniform vote) when max unchanged.
// ---------------------------------------------------------------------------
#define KV_ROWB   144                 // bytes per smem row (72 halves)
#define KSTAGE_B  (64 * KV_ROWB)      // 9216 B
#define VSTAGE_B  (72 * KV_ROWB)      // 10368 B (64 data + 8 ones/zero rows)
#define ATTN_SMEM (4 * (KSTAGE_B + VSTAGE_B))   // 78336 B

__global__ void __launch_bounds__(256, 2) k_attn() {
    extern __shared__ __half smem[];

    const int t    = threadIdx.x;
    const int w    = t >> 5;
    const int lane = t & 31;
    const int gr   = lane >> 2;
    const int gc   = lane & 3;

    const int bh = blockIdx.y;
    const int b  = bh >> 2, h = bh & 3;
    const int i0 = blockIdx.x * 128;
    const int iw = i0 + w * 16;

    const __half* Qg = g_qkvh + ((size_t)b * 768 +       h * DH) * HW;
    const __half* Kg = g_qkvh + ((size_t)b * 768 + 256 + h * DH) * HW;
    const __half* Vg = g_qkvh + ((size_t)b * 768 + 512 + h * DH) * HW;

    const unsigned ks_u = (unsigned)__cvta_generic_to_shared(smem);
    const unsigned vb_u = ks_u + 4 * KSTAGE_B;

    const int fr = t >> 2;              // fill row 0..63
    const int fc = (t & 3) * 2;         // fill chunk base

    const unsigned vrow = (lane >> 4) * 8 + (lane & 7);
    const unsigned vAoff = vrow * KV_ROWB + ((lane >> 3) & 1) * 16;
    const unsigned vSoff = (64 + (lane & 7)) * KV_ROWB + ((lane >> 3) & 1) * 16;
    const unsigned kAoff = lane * KV_ROWB;

    // init ones/zero rows (64..71) of all 4 V stages
    {
        __half* Vb = smem + 4 * 64 * 72;   // halves
        const __half one = __float2half(1.f);
        const __half zer = __float2half(0.f);
        for (int i = t; i < 4 * 8 * 72; i += 256) {
            int s  = i / (8 * 72);
            int rm = i % (8 * 72);
            int r  = rm / 72, cc = rm % 72;
            Vb[s * (72 * 72) + (64 + r) * 72 + cc] = (r == 0) ? one : zer;
        }
    }

    // Q A-fragments (already scaled in GEMM epilogue)
    unsigned Aq[4][4];
    #pragma unroll
    for (int kk = 0; kk < 4; kk++) {
        const int c0 = kk * 16 + 2 * gc;
        #pragma unroll
        for (int half8 = 0; half8 < 2; half8++) {
            const int c = c0 + half8 * 8;
            Aq[kk][half8 * 2 + 0] = h2u(__halves2half2(Qg[(size_t)(c    ) * HW + iw + gr],
                                                       Qg[(size_t)(c + 1) * HW + iw + gr]));
            Aq[kk][half8 * 2 + 1] = h2u(__halves2half2(Qg[(size_t)(c    ) * HW + iw + gr + 8],
                                                       Qg[(size_t)(c + 1) * HW + iw + gr + 8]));
        }
    }

    float Oacc[8][4];
    #pragma unroll
    for (int i = 0; i < 8; i++) {
        Oacc[i][0] = 0.f; Oacc[i][1] = 0.f; Oacc[i][2] = 0.f; Oacc[i][3] = 0.f;
    }
    float Osum[4] = {0.f, 0.f, 0.f, 0.f};
    float m0 = -CUDART_INF_F, m1 = -CUDART_INF_F;

    // prefetch tiles 0,1
    #pragma unroll
    for (int pf = 0; pf < 2; pf++) {
        const int j0 = pf * 64;
        const unsigned sk = ks_u + pf * KSTAGE_B;
        const unsigned sv = vb_u + pf * VSTAGE_B;
        cpa16(sk + fr * KV_ROWB + (fc    ) * 16, Kg + (size_t)fr * HW + j0 + (fc    ) * 8);
        cpa16(sk + fr * KV_ROWB + (fc + 1) * 16, Kg + (size_t)fr * HW + j0 + (fc + 1) * 8);
        cpa16(sv + fr * KV_ROWB + (fc    ) * 16, Vg + (size_t)fr * HW + j0 + (fc    ) * 8);
        cpa16(sv + fr * KV_ROWB + (fc + 1) * 16, Vg + (size_t)fr * HW + j0 + (fc + 1) * 8);
        CP_COMMIT();
    }

    for (int jt = 0; jt < 64; jt++) {
        if (jt + 2 < 64) {
            const int j0 = (jt + 2) * 64;
            const unsigned sk = ks_u + ((jt + 2) & 3) * KSTAGE_B;
            const unsigned sv = vb_u + ((jt + 2) & 3) * VSTAGE_B;
            cpa16(sk + fr * KV_ROWB + (fc    ) * 16, Kg + (size_t)fr * HW + j0 + (fc    ) * 8);
            cpa16(sk + fr * KV_ROWB + (fc + 1) * 16, Kg + (size_t)fr * HW + j0 + (fc + 1) * 8);
            cpa16(sv + fr * KV_ROWB + (fc    ) * 16, Vg + (size_t)fr * HW + j0 + (fc    ) * 8);
            cpa16(sv + fr * KV_ROWB + (fc + 1) * 16, Vg + (size_t)fr * HW + j0 + (fc + 1) * 8);
        }
        CP_COMMIT();
        CP_WAIT(2);
        __syncthreads();

        const unsigned kA = ks_u + (jt & 3) * KSTAGE_B + kAoff;
        const unsigned vA = vb_u + (jt & 3) * VSTAGE_B + vAoff;
        const unsigned vS = vb_u + (jt & 3) * VSTAGE_B + vSoff;

        // ---- S = Q K^T ----
        float S[8][4];
        #pragma unroll
        for (int nt = 0; nt < 8; nt++) {
            S[nt][0] = 0.f; S[nt][1] = 0.f; S[nt][2] = 0.f; S[nt][3] = 0.f;
        }
        #pragma unroll
        for (int nt = 0; nt < 8; nt++) {
            unsigned kb[4];
            ldmx4_t(kb, kA + nt * 16);
            mma_f16(S[nt], Aq[0], kb[0], kb[1]);
            mma_f16(S[nt], Aq[1], kb[2], kb[3]);
            ldmx4_t(kb, kA + 32 * KV_ROWB + nt * 16);
            mma_f16(S[nt], Aq[2], kb[0], kb[1]);
            mma_f16(S[nt], Aq[3], kb[2], kb[3]);
        }

        // ---- max update (fp32) ----
        float mx0 = -CUDART_INF_F, mx1 = -CUDART_INF_F;
        #pragma unroll
        for (int nt = 0; nt < 8; nt++) {
            mx0 = fmaxf(mx0, fmaxf(S[nt][0], S[nt][1]));
            mx1 = fmaxf(mx1, fmaxf(S[nt][2], S[nt][3]));
        }
        mx0 = fmaxf(mx0, __shfl_xor_sync(0xffffffffu, mx0, 1));
        mx0 = fmaxf(mx0, __shfl_xor_sync(0xffffffffu, mx0, 2));
        mx1 = fmaxf(mx1, __shfl_xor_sync(0xffffffffu, mx1, 1));
        mx1 = fmaxf(mx1, __shfl_xor_sync(0xffffffffu, mx1, 2));

        const float mn0 = fmaxf(m0, mx0);
        const float mn1 = fmaxf(m1, mx1);
        const bool nochange = (mn0 == m0) & (mn1 == m1);

        // ---- P = ex2(S - mn) in packed half ----
        unsigned Ph0[8], Ph1[8];
        #pragma unroll
        for (int nt = 0; nt < 8; nt++) {
            Ph0[nt] = ex2h2(h2u(__floats2half2_rn(S[nt][0] - mn0, S[nt][1] - mn0)));
            Ph1[nt] = ex2h2(h2u(__floats2half2_rn(S[nt][2] - mn1, S[nt][3] - mn1)));
        }

        // ---- rescale accumulators only when max changed (warp-uniform) ----
        if (!__all_sync(0xffffffffu, nochange)) {
            const float al0 = ex2f(m0 - mn0);
            const float al1 = ex2f(m1 - mn1);
            #pragma unroll
            for (int ct = 0; ct < 8; ct++) {
                Oacc[ct][0] *= al0; Oacc[ct][1] *= al0;
                Oacc[ct][2] *= al1; Oacc[ct][3] *= al1;
            }
            Osum[0] *= al0; Osum[1] *= al0;
            Osum[2] *= al1; Osum[3] *= al1;
        }
        m0 = mn0; m1 = mn1;

        // ---- O += P V^T ; l via ones-channel ----
        #pragma unroll
        for (int kk = 0; kk < 4; kk++) {
            unsigned pa[4];
            pa[0] = Ph0[2*kk];   pa[1] = Ph1[2*kk];
            pa[2] = Ph0[2*kk+1]; pa[3] = Ph1[2*kk+1];
            #pragma unroll
            for (int ct = 0; ct < 8; ct += 2) {
                unsigned vb[4];
                ldmx4(vb, vA + ct * (8 * KV_ROWB) + kk * 32);
                mma_f16(Oacc[ct    ], pa, vb[0], vb[1]);
                mma_f16(Oacc[ct + 1], pa, vb[2], vb[3]);
            }
            unsigned sbv[2];
            ldmx2(sbv, vS + kk * 32);
            mma_f16(Osum, pa, sbv[0], sbv[1]);
        }
    }

    // ---- epilogue: l from sum channel (gc==0 lanes), normalize, write ----
    const float lA = __shfl_sync(0xffffffffu, Osum[0], lane & 28);
    const float lB = __shfl_sync(0xffffffffu, Osum[2], lane & 28);
    const float inv0 = 1.f / lA;
    const float inv1 = 1.f / lB;
    __half* Og = g_oh + ((size_t)b * CCH + h * DH) * HW;
    #pragma unroll
    for (int ct = 0; ct < 8; ct++) {
        const int c = ct * 8 + 2 * gc;
        Og[(size_t)(c    ) * HW + iw + gr    ] = __float2half(Oacc[ct][0] * inv0);
        Og[(size_t)(c + 1) * HW + iw + gr    ] = __float2half(Oacc[ct][1] * inv0);
        Og[(size_t)(c    ) * HW + iw + gr + 8] = __float2half(Oacc[ct][2] * inv1);
        Og[(size_t)(c + 1) * HW + iw + gr + 8] = __float2half(Oacc[ct][3] * inv1);
    }
}

// ---------------------------------------------------------------------------
extern "C" void kernel_launch(void* const* d_in, const int* in_sizes, int n_in,
                              void* d_out, int out_size) {
    const float* x      = (const float*)d_in[0];
    const float* norm_w = (const float*)d_in[1];
    const float* norm_b = (const float*)d_in[2];
    const float* qkv_w  = (const float*)d_in[3];
    const float* qkv_b  = (const float*)d_in[4];
    const float* proj_w = (const float*)d_in[5];
    const float* proj_b = (const float*)d_in[6];
    float* out = (float*)d_out;

    cudaFuncSetAttribute(k_attn, cudaFuncAttributeMaxDynamicSharedMemorySize, ATTN_SMEM);
    cudaFuncSetAttribute(k_gemm_h<0>, cudaFuncAttributeMaxDynamicSharedMemorySize, GEMM_SMEM);
    cudaFuncSetAttribute(k_gemm_h<1>, cudaFuncAttributeMaxDynamicSharedMemorySize, GEMM_SMEM);

    k_stats<<<256, 256>>>(x);
    k_coef<<<4, 256>>>(norm_w, norm_b);
    k_xh<<<2304, 256>>>(x, qkv_w, proj_w);
    k_gemm_h<0><<<dim3(32, 6, BB), 256, GEMM_SMEM>>>(qkv_b, nullptr, nullptr);
    k_attn<<<dim3(HW/128, BB*NH), 256, ATTN_SMEM>>>();
    k_gemm_h<1><<<dim3(32, 2, BB), 256, GEMM_SMEM>>>(proj_b, x, out);
}